// round 8
// baseline (speedup 1.0000x reference)
#include <cuda_runtime.h>
#include <cstdint>

#define NB   8
#define CC   256
#define HH   56
#define WWd  56
#define HWP  3136
#define PPAD 3200
#define K7   7
#define CKD  1792

// Scratch
__device__ float g_Xp [NB * CC  * PPAD];   //  26 MB  A1
__device__ float g_T5 [NB * CKD * PPAD];   // 184 MB  B1 (p contiguous)
__device__ float g_T6t[NB * PPAD * CKD];   // 184 MB  B2 transposed (q contiguous)
__device__ float g_T7 [NB * CC  * CKD];    //  15 MB  A2 (q contiguous)

__device__ __forceinline__ uint32_t smem_u32(const void* p) {
    uint32_t a;
    asm("{ .reg .u64 t; cvta.to.shared.u64 t, %1; cvt.u32.u64 %0, t; }" : "=r"(a) : "l"(p));
    return a;
}
__device__ __forceinline__ float rna_tf32(float x) {
    uint32_t r;
    asm("cvt.rna.tf32.f32 %0, %1;" : "=r"(r) : "f"(x));
    return __uint_as_float(r);
}
__device__ __forceinline__ uint32_t lds32(uint32_t a) {
    uint32_t v;
    asm volatile("ld.shared.b32 %0, [%1];" : "=r"(v) : "r"(a));
    return v;
}
#define CP_ASYNC16(dst, src) \
    asm volatile("cp.async.cg.shared.global [%0], [%1], 16;" :: "r"(dst), "l"(src))
#define CP_COMMIT() asm volatile("cp.async.commit_group;")
#define CP_WAIT1()  asm volatile("cp.async.wait_group 1;" ::: "memory")

// ---------------- prep ----------------
__global__ void prep_xp_kernel(const float* __restrict__ x) {
    int idx = blockIdx.x * blockDim.x + threadIdx.x;
    if (idx >= NB * CC * PPAD) return;
    int p  = idx % PPAD;
    int nc = idx / PPAD;
    g_Xp[idx] = (p < HWP) ? rna_tf32(x[nc * HWP + p]) : 0.0f;
}

// Fused: writes T5[n,q,p] (p-contiguous) and T6t[n,p,q] (q-contiguous via smem transpose)
__global__ __launch_bounds__(256) void prep_t56_kernel(const float* __restrict__ x,
                                                       const float* __restrict__ p1w) {
    __shared__ float ts[64][33];
    int p0 = blockIdx.x * 32;
    int q0 = blockIdx.y * 64;
    int n  = blockIdx.z;
    int t  = threadIdx.x;
    int tp = t & 31;
    int tq = t >> 5;

    const float* xn = x + n * CC * HWP;
    int p = p0 + tp;
    bool pv = (p < HWP);
    int h = p / WWd, w = p % WWd;
    int hh = (h + HH - 1) % HH;
    int w2 = (w + 1) % WWd;
    float* t5n = g_T5 + ((long)n * CKD) * PPAD;

#pragma unroll
    for (int qi = 0; qi < 8; qi++) {
        int ql = tq + 8 * qi;
        int q = q0 + ql;
        float v5 = 0.0f, v6 = 0.0f;
        if (pv) {
            int j = q / K7, k = q % K7;
            int jm = (j + CC - 1) % CC;
            float xv  = xn[j * HWP + p];
            float t1  = p1w[j * HWP + p] * xv;
            float t3 = 0.0f;
            int wk = w + k - 3;
            if (wk >= 0 && wk < WWd) {
                int pp = h * WWd + wk;
                t3 = p1w[jm * HWP + pp] * xn[jm * HWP + pp];
            }
            float t4 = 0.0f;
            int wk2 = w2 + k - 3;
            if (wk2 >= 0 && wk2 < WWd) {
                int pp = hh * WWd + wk2;
                t4 = p1w[jm * HWP + pp] * xn[jm * HWP + pp];
            }
            v5 = rna_tf32(t1 - t3);
            v6 = rna_tf32(xv + t4);
        }
        t5n[(long)q * PPAD + p] = v5;
        ts[ql][tp] = v6;
    }
    __syncthreads();

    int ql = t & 63;
    int pl = t >> 6;
    float* dst = g_T6t + ((long)n * PPAD) * CKD;
#pragma unroll
    for (int pi = 0; pi < 8; pi++) {
        int prow = p0 + pl + 4 * pi;
        dst[(long)prow * CKD + q0 + ql] = ts[ql][pl + 4 * pi];
    }
}

// ---------------- TF32 mma.sync GEMM (NT): C = scale * A(MxK) * B(NxK)^T ----------------
// CTA 256 thr, block 128x128xBK32, 8 warps (4m x 2n), warp 32x64 = 2x8 m16n8k8.
// 3 stages x 32KB = 96KB, regs<=128 -> 2 CTAs/SM (16 warps/SM).
// Smem elem (row,k) at row*128 + ((k*4)^((row&7)<<4)): conflict-free LDS.32 frags.
__global__ __launch_bounds__(256, 2)
void gemm_mma(const float* __restrict__ A, const float* __restrict__ B, float* __restrict__ C,
              int K, int KT, long sAz, long sBz, long sCz, int ldc, float scale,
              int nvalid, int round_out) {
    extern __shared__ __align__(1024) char smem[];
    const uint32_t STGB = 32768;   // 16KB A + 16KB B per stage
    uint32_t sb = smem_u32(smem);

    int tid = threadIdx.x, lane = tid & 31, wid = tid >> 5;
    int g = lane >> 2, t = lane & 3;
    int mwarp = (wid & 3) * 32, nwarp = (wid >> 2) * 64;

    const float* Ab = A + (long)blockIdx.z * sAz + (long)(blockIdx.x * 128) * K;
    const float* Bb = B + (long)blockIdx.z * sBz + (long)(blockIdx.y * 128) * K;

    // staging: threads 0-127 stage A rows, 128-255 stage B rows (8 granules each)
    int srow = tid & 127;
    const char* src = (const char*)(((tid < 128) ? Ab : Bb) + (long)srow * K);
    uint32_t dst = sb + ((tid < 128) ? 0u : 16384u) + (uint32_t)srow * 128;
    uint32_t swz = (srow & 7) * 16;

    float c[2][8][4];
#pragma unroll
    for (int mi = 0; mi < 2; mi++)
#pragma unroll
        for (int ni = 0; ni < 8; ni++)
#pragma unroll
            for (int e = 0; e < 4; e++) c[mi][ni][e] = 0.0f;

    // prologue: stages 0,1
#pragma unroll
    for (int s = 0; s < 2; s++) {
        uint32_t st = s * STGB;
        long go = (long)s * 128;
#pragma unroll
        for (int j = 0; j < 8; j++)
            CP_ASYNC16(dst + st + (uint32_t)((j * 16) ^ swz), src + go + j * 16);
        CP_COMMIT();
    }

    int buf = 0;
#pragma unroll 1
    for (int kt = 0; kt < KT; kt++) {
        CP_WAIT1();
        __syncthreads();
        if (kt + 2 < KT) {
            int b2 = buf + 2; if (b2 >= 3) b2 -= 3;
            uint32_t st = (uint32_t)b2 * STGB;
            long go = (long)(kt + 2) * 128;
#pragma unroll
            for (int j = 0; j < 8; j++)
                CP_ASYNC16(dst + st + (uint32_t)((j * 16) ^ swz), src + go + j * 16);
        }
        CP_COMMIT();

        uint32_t sA = sb + (uint32_t)buf * STGB;
        uint32_t sB = sA + 16384;
#pragma unroll
        for (int kk = 0; kk < 4; kk++) {
            int k0 = kk * 8;
            uint32_t kx1 = (uint32_t)(((k0 + t) * 4) ^ (g << 4));
            uint32_t kx2 = (uint32_t)(((k0 + t + 4) * 4) ^ (g << 4));
            uint32_t a[2][4];
#pragma unroll
            for (int mi = 0; mi < 2; mi++) {
                uint32_t b0 = sA + (uint32_t)((mwarp + mi * 16 + g) * 128);
                uint32_t b1 = b0 + 8 * 128;
                a[mi][0] = lds32(b0 + kx1);
                a[mi][1] = lds32(b1 + kx1);
                a[mi][2] = lds32(b0 + kx2);
                a[mi][3] = lds32(b1 + kx2);
            }
            uint32_t b[8][2];
#pragma unroll
            for (int ni = 0; ni < 8; ni++) {
                uint32_t nb = sB + (uint32_t)((nwarp + ni * 8 + g) * 128);
                b[ni][0] = lds32(nb + kx1);
                b[ni][1] = lds32(nb + kx2);
            }
#pragma unroll
            for (int mi = 0; mi < 2; mi++)
#pragma unroll
                for (int ni = 0; ni < 8; ni++) {
                    asm volatile(
                        "mma.sync.aligned.m16n8k8.row.col.f32.tf32.tf32.f32 "
                        "{%0,%1,%2,%3}, {%4,%5,%6,%7}, {%8,%9}, {%0,%1,%2,%3};"
                        : "+f"(c[mi][ni][0]), "+f"(c[mi][ni][1]),
                          "+f"(c[mi][ni][2]), "+f"(c[mi][ni][3])
                        : "r"(a[mi][0]), "r"(a[mi][1]), "r"(a[mi][2]), "r"(a[mi][3]),
                          "r"(b[ni][0]), "r"(b[ni][1]));
                }
        }
        buf++; if (buf >= 3) buf = 0;
    }

    // epilogue
    float* Cz = C + (long)blockIdx.z * sCz;
    int colbase = blockIdx.y * 128 + nwarp;
#pragma unroll
    for (int mi = 0; mi < 2; mi++) {
        int row0 = blockIdx.x * 128 + mwarp + mi * 16 + g;
        int row1 = row0 + 8;
#pragma unroll
        for (int ni = 0; ni < 8; ni++) {
            int col = colbase + ni * 8 + 2 * t;
            if (col < nvalid) {
                float2 v0, v1;
                v0.x = c[mi][ni][0] * scale; v0.y = c[mi][ni][1] * scale;
                v1.x = c[mi][ni][2] * scale; v1.y = c[mi][ni][3] * scale;
                if (round_out) {
                    v0.x = rna_tf32(v0.x); v0.y = rna_tf32(v0.y);
                    v1.x = rna_tf32(v1.x); v1.y = rna_tf32(v1.y);
                }
                *(float2*)(Cz + (long)row0 * ldc + col) = v0;
                *(float2*)(Cz + (long)row1 * ldc + col) = v1;
            }
        }
    }
}

// ---------------- launch ----------------
extern "C" void kernel_launch(void* const* d_in, const int* in_sizes, int n_in,
                              void* d_out, int out_size) {
    (void)in_sizes; (void)n_in; (void)out_size;
    const float* x   = (const float*)d_in[0];
    const float* p1w = (const float*)d_in[1];
    float* out = (float*)d_out;

    const int SMEM = 3 * 32768;  // 96 KB -> 2 CTAs/SM
    cudaFuncSetAttribute(gemm_mma, cudaFuncAttributeMaxDynamicSharedMemorySize, SMEM);

    {
        int total = NB * CC * PPAD;
        prep_xp_kernel<<<(total + 255) / 256, 256>>>(x);
    }
    prep_t56_kernel<<<dim3(PPAD / 32, CKD / 64, NB), 256>>>(x, p1w);

    float *T7, *Xp, *T5, *T6t;
    cudaGetSymbolAddress((void**)&T7,  g_T7);
    cudaGetSymbolAddress((void**)&Xp,  g_Xp);
    cudaGetSymbolAddress((void**)&T5,  g_T5);
    cudaGetSymbolAddress((void**)&T6t, g_T6t);

    // GEMM1: T7[i,q] = (1/56) * sum_p Xp[i,p]*T5[q,p];  M=256,N=1792,K=3200
    gemm_mma<<<dim3(CC / 128, CKD / 128, NB), 256, SMEM>>>(
        Xp, T5, T7, PPAD, PPAD / 32,
        (long)CC * PPAD, (long)CKD * PPAD, (long)CC * CKD,
        CKD, 1.0f / 56.0f, CKD, 1);

    // GEMM2: out[i,p] = (1/sqrt(1792)) * sum_q T7[i,q]*T6t[p,q];  M=256,N=3200,K=1792
    gemm_mma<<<dim3(CC / 128, PPAD / 128, NB), 256, SMEM>>>(
        T7, T6t, out, CKD, CKD / 32,
        (long)CC * CKD, (long)PPAD * CKD, (long)CC * HWP,
        HWP, 0.0236227795f, HWP, 0);
}

// round 9
// speedup vs baseline: 1.0594x; 1.0594x over previous
#include <cuda_runtime.h>
#include <cstdint>

#define NB   8
#define CC   256
#define HH   56
#define WWd  56
#define HWP  3136
#define PPAD 3200
#define K7   7
#define CKD  1792

// Scratch
__device__ float g_Xp [NB * CC  * PPAD];   //  26 MB  A1
__device__ float g_T5 [NB * CKD * PPAD];   // 184 MB  B1 (p contiguous)
__device__ float g_T6t[NB * PPAD * CKD];   // 184 MB  B2 transposed (q contiguous)
__device__ float g_T7 [NB * CC  * CKD];    //  15 MB  A2 (q contiguous)

__device__ __forceinline__ uint32_t smem_u32(const void* p) {
    uint32_t a;
    asm("{ .reg .u64 t; cvta.to.shared.u64 t, %1; cvt.u32.u64 %0, t; }" : "=r"(a) : "l"(p));
    return a;
}
__device__ __forceinline__ float rna_tf32(float x) {
    uint32_t r;
    asm("cvt.rna.tf32.f32 %0, %1;" : "=r"(r) : "f"(x));
    return __uint_as_float(r);
}
#define CP_ASYNC16(dst, src) \
    asm volatile("cp.async.cg.shared.global [%0], [%1], 16;" :: "r"(dst), "l"(src))
#define CP_COMMIT() asm volatile("cp.async.commit_group;")
#define CP_WAIT1()  asm volatile("cp.async.wait_group 1;" ::: "memory")

// ---------------- prep ----------------
__global__ void prep_xp_kernel(const float* __restrict__ x) {
    int idx = blockIdx.x * blockDim.x + threadIdx.x;
    if (idx >= NB * CC * PPAD) return;
    int p  = idx % PPAD;
    int nc = idx / PPAD;
    g_Xp[idx] = (p < HWP) ? rna_tf32(x[nc * HWP + p]) : 0.0f;
}

// Fused: writes T5[n,q,p] (p-contiguous) and T6t[n,p,q] (q-contiguous via smem transpose)
__global__ __launch_bounds__(256) void prep_t56_kernel(const float* __restrict__ x,
                                                       const float* __restrict__ p1w) {
    __shared__ float ts[64][33];
    int p0 = blockIdx.x * 32;
    int q0 = blockIdx.y * 64;
    int n  = blockIdx.z;
    int t  = threadIdx.x;
    int tp = t & 31;
    int tq = t >> 5;

    const float* xn = x + n * CC * HWP;
    int p = p0 + tp;
    bool pv = (p < HWP);
    int h = p / WWd, w = p % WWd;
    int hh = (h + HH - 1) % HH;
    int w2 = (w + 1) % WWd;
    float* t5n = g_T5 + ((long)n * CKD) * PPAD;

#pragma unroll
    for (int qi = 0; qi < 8; qi++) {
        int ql = tq + 8 * qi;
        int q = q0 + ql;
        float v5 = 0.0f, v6 = 0.0f;
        if (pv) {
            int j = q / K7, k = q % K7;
            int jm = (j + CC - 1) % CC;
            float xv  = xn[j * HWP + p];
            float t1  = p1w[j * HWP + p] * xv;
            float t3 = 0.0f;
            int wk = w + k - 3;
            if (wk >= 0 && wk < WWd) {
                int pp = h * WWd + wk;
                t3 = p1w[jm * HWP + pp] * xn[jm * HWP + pp];
            }
            float t4 = 0.0f;
            int wk2 = w2 + k - 3;
            if (wk2 >= 0 && wk2 < WWd) {
                int pp = hh * WWd + wk2;
                t4 = p1w[jm * HWP + pp] * xn[jm * HWP + pp];
            }
            v5 = rna_tf32(t1 - t3);
            v6 = rna_tf32(xv + t4);
        }
        t5n[(long)q * PPAD + p] = v5;
        ts[ql][tp] = v6;
    }
    __syncthreads();

    int ql = t & 63;
    int pl = t >> 6;
    float* dst = g_T6t + ((long)n * PPAD) * CKD;
#pragma unroll
    for (int pi = 0; pi < 8; pi++) {
        int prow = p0 + pl + 4 * pi;
        dst[(long)prow * CKD + q0 + ql] = ts[ql][pl + 4 * pi];
    }
}

// ---------------- TF32 mma.sync GEMM (NT): C = scale * A(MxK) * B(NxK)^T ----------------
// CTA 256 thr, block 128x128xBK32, 8 warps (2m x 4n), warp 64x32 = 4x4 m16n8k8.
// Fragments via ldmatrix.b16 (tf32 trick): 8 ldmatrix per warp-k8 instead of 24 LDS.32.
// 3 stages x 32KB = 96KB -> 2 CTAs/SM. Smem elem (row,k) at row*128 + ((k*4)^((row&7)<<4)).
__global__ __launch_bounds__(256, 2)
void gemm_mma(const float* __restrict__ A, const float* __restrict__ B, float* __restrict__ C,
              int K, int KT, long sAz, long sBz, long sCz, int ldc, float scale,
              int nvalid, int round_out) {
    extern __shared__ __align__(1024) char smem[];
    const uint32_t STGB = 32768;   // 16KB A + 16KB B per stage
    uint32_t sb = smem_u32(smem);

    int tid = threadIdx.x, lane = tid & 31, wid = tid >> 5;
    int g = lane >> 2, t = lane & 3;
    int mwarp = (wid & 1) * 64, nwarp = (wid >> 1) * 32;

    const float* Ab = A + (long)blockIdx.z * sAz + (long)(blockIdx.x * 128) * K;
    const float* Bb = B + (long)blockIdx.z * sBz + (long)(blockIdx.y * 128) * K;

    // staging: threads 0-127 stage A rows, 128-255 stage B rows (8 granules each)
    int srow = tid & 127;
    const char* src = (const char*)(((tid < 128) ? Ab : Bb) + (long)srow * K);
    uint32_t dst = sb + ((tid < 128) ? 0u : 16384u) + (uint32_t)srow * 128;
    uint32_t swz = (srow & 7) * 16;

    // ldmatrix per-lane row bases (within-stage offsets)
    // A x4: lane supplies row m = mwarp + mi*16 + (lane&15); col granule = kk*32 + ((lane>>4)<<4)
    uint32_t aRow[4], aSwz[4];
#pragma unroll
    for (int mi = 0; mi < 4; mi++) {
        int m = mwarp + mi * 16 + (lane & 15);
        aRow[mi] = (uint32_t)(m * 128);
        aSwz[mi] = (uint32_t)((m & 7) << 4);
    }
    uint32_t aKbit = (uint32_t)((lane >> 4) << 4);
    // B x2: lane supplies row n = nwarp + ni*8 + (lane&7); col granule = kk*32 + (((lane>>3)&1)<<4)
    uint32_t bRow[4], bSwz[4];
#pragma unroll
    for (int ni = 0; ni < 4; ni++) {
        int n = nwarp + ni * 8 + (lane & 7);
        bRow[ni] = (uint32_t)(16384 + n * 128);
        bSwz[ni] = (uint32_t)((n & 7) << 4);
    }
    uint32_t bKbit = (uint32_t)(((lane >> 3) & 1) << 4);

    float c[4][4][4];
#pragma unroll
    for (int mi = 0; mi < 4; mi++)
#pragma unroll
        for (int ni = 0; ni < 4; ni++)
#pragma unroll
            for (int e = 0; e < 4; e++) c[mi][ni][e] = 0.0f;

    // prologue: stages 0,1
#pragma unroll
    for (int s = 0; s < 2; s++) {
        uint32_t st = s * STGB;
        long go = (long)s * 128;
#pragma unroll
        for (int j = 0; j < 8; j++)
            CP_ASYNC16(dst + st + (uint32_t)((j * 16) ^ swz), src + go + j * 16);
        CP_COMMIT();
    }

    int buf = 0;
#pragma unroll 1
    for (int kt = 0; kt < KT; kt++) {
        CP_WAIT1();
        __syncthreads();
        if (kt + 2 < KT) {
            int b2 = buf + 2; if (b2 >= 3) b2 -= 3;
            uint32_t st = (uint32_t)b2 * STGB;
            long go = (long)(kt + 2) * 128;
#pragma unroll
            for (int j = 0; j < 8; j++)
                CP_ASYNC16(dst + st + (uint32_t)((j * 16) ^ swz), src + go + j * 16);
        }
        CP_COMMIT();

        uint32_t stg = sb + (uint32_t)buf * STGB;
#pragma unroll
        for (int kk = 0; kk < 4; kk++) {
            uint32_t akOff = (uint32_t)(kk * 32) + aKbit;
            uint32_t bkOff = (uint32_t)(kk * 32) + bKbit;
            uint32_t a[4][4];
#pragma unroll
            for (int mi = 0; mi < 4; mi++) {
                uint32_t addr = stg + aRow[mi] + (akOff ^ aSwz[mi]);
                asm volatile(
                    "ldmatrix.sync.aligned.m8n8.x4.shared.b16 {%0,%1,%2,%3}, [%4];"
                    : "=r"(a[mi][0]), "=r"(a[mi][1]), "=r"(a[mi][2]), "=r"(a[mi][3])
                    : "r"(addr));
            }
            uint32_t b[4][2];
#pragma unroll
            for (int ni = 0; ni < 4; ni++) {
                uint32_t addr = stg + bRow[ni] + (bkOff ^ bSwz[ni]);
                asm volatile(
                    "ldmatrix.sync.aligned.m8n8.x2.shared.b16 {%0,%1}, [%2];"
                    : "=r"(b[ni][0]), "=r"(b[ni][1])
                    : "r"(addr));
            }
#pragma unroll
            for (int mi = 0; mi < 4; mi++)
#pragma unroll
                for (int ni = 0; ni < 4; ni++) {
                    asm volatile(
                        "mma.sync.aligned.m16n8k8.row.col.f32.tf32.tf32.f32 "
                        "{%0,%1,%2,%3}, {%4,%5,%6,%7}, {%8,%9}, {%0,%1,%2,%3};"
                        : "+f"(c[mi][ni][0]), "+f"(c[mi][ni][1]),
                          "+f"(c[mi][ni][2]), "+f"(c[mi][ni][3])
                        : "r"(a[mi][0]), "r"(a[mi][1]), "r"(a[mi][2]), "r"(a[mi][3]),
                          "r"(b[ni][0]), "r"(b[ni][1]));
                }
        }
        buf++; if (buf >= 3) buf = 0;
    }

    // epilogue
    float* Cz = C + (long)blockIdx.z * sCz;
    int colbase = blockIdx.y * 128 + nwarp;
#pragma unroll
    for (int mi = 0; mi < 4; mi++) {
        int row0 = blockIdx.x * 128 + mwarp + mi * 16 + g;
        int row1 = row0 + 8;
#pragma unroll
        for (int ni = 0; ni < 4; ni++) {
            int col = colbase + ni * 8 + 2 * t;
            if (col < nvalid) {
                float2 v0, v1;
                v0.x = c[mi][ni][0] * scale; v0.y = c[mi][ni][1] * scale;
                v1.x = c[mi][ni][2] * scale; v1.y = c[mi][ni][3] * scale;
                if (round_out) {
                    v0.x = rna_tf32(v0.x); v0.y = rna_tf32(v0.y);
                    v1.x = rna_tf32(v1.x); v1.y = rna_tf32(v1.y);
                }
                *(float2*)(Cz + (long)row0 * ldc + col) = v0;
                *(float2*)(Cz + (long)row1 * ldc + col) = v1;
            }
        }
    }
}

// ---------------- launch ----------------
extern "C" void kernel_launch(void* const* d_in, const int* in_sizes, int n_in,
                              void* d_out, int out_size) {
    (void)in_sizes; (void)n_in; (void)out_size;
    const float* x   = (const float*)d_in[0];
    const float* p1w = (const float*)d_in[1];
    float* out = (float*)d_out;

    const int SMEM = 3 * 32768;  // 96 KB -> 2 CTAs/SM
    cudaFuncSetAttribute(gemm_mma, cudaFuncAttributeMaxDynamicSharedMemorySize, SMEM);

    {
        int total = NB * CC * PPAD;
        prep_xp_kernel<<<(total + 255) / 256, 256>>>(x);
    }
    prep_t56_kernel<<<dim3(PPAD / 32, CKD / 64, NB), 256>>>(x, p1w);

    float *T7, *Xp, *T5, *T6t;
    cudaGetSymbolAddress((void**)&T7,  g_T7);
    cudaGetSymbolAddress((void**)&Xp,  g_Xp);
    cudaGetSymbolAddress((void**)&T5,  g_T5);
    cudaGetSymbolAddress((void**)&T6t, g_T6t);

    // GEMM1: T7[i,q] = (1/56) * sum_p Xp[i,p]*T5[q,p];  M=256,N=1792,K=3200
    gemm_mma<<<dim3(CC / 128, CKD / 128, NB), 256, SMEM>>>(
        Xp, T5, T7, PPAD, PPAD / 32,
        (long)CC * PPAD, (long)CKD * PPAD, (long)CC * CKD,
        CKD, 1.0f / 56.0f, CKD, 1);

    // GEMM2: out[i,p] = (1/sqrt(1792)) * sum_q T7[i,q]*T6t[p,q];  M=256,N=3200,K=1792
    gemm_mma<<<dim3(CC / 128, PPAD / 128, NB), 256, SMEM>>>(
        T7, T6t, out, CKD, CKD / 32,
        (long)CC * CKD, (long)PPAD * CKD, (long)CC * HWP,
        HWP, 0.0236227795f, HWP, 0);
}

// round 11
// speedup vs baseline: 1.1131x; 1.0506x over previous
#include <cuda_runtime.h>
#include <cstdint>

#define NB   8
#define CC   256
#define HH   56
#define WWd  56
#define HWP  3136
#define PPAD 3200
#define K7   7
#define CKD  1792     // 7*256

// ---------------- scratch ----------------
__device__ float g_A1 [NB * CKD * HWP];   // 180 MB: stacked shifted x, rows (k*256+i), K=p
__device__ float g_T2 [NB * CC  * HWP];   //  26 MB: t2[j,p] K-major
__device__ float g_T2t[NB * PPAD * CC];   //  26 MB: t2^T [p,j], zero-padded p>=3136
__device__ float g_Xt [NB * PPAD * CC];   //  26 MB: x^T  [p,j], zero-padded
__device__ float g_S  [2 * NB * CKD * CC];//  29 MB: GEMM-A split-K partials
__device__ float g_A2 [NB * CKD * CC];    //  15 MB: t7 rows (k*256+i), K=j
__device__ float g_U  [NB * CC * CC];     //   2 MB: sum_k t7
__device__ float g_W  [NB * CKD * PPAD];  // 184 MB: GEMM-B out
__device__ float g_O1 [NB * CC * PPAD];   //  26 MB: U*x

__device__ __forceinline__ uint32_t smem_u32(const void* p) {
    uint32_t a;
    asm("{ .reg .u64 t; cvta.to.shared.u64 t, %1; cvt.u32.u64 %0, t; }" : "=r"(a) : "l"(p));
    return a;
}
__device__ __forceinline__ float rna_tf32(float x) {
    uint32_t r;
    asm("cvt.rna.tf32.f32 %0, %1;" : "=r"(r) : "f"(x));
    return __uint_as_float(r);
}
#define CP_ASYNC16(dst, src) \
    asm volatile("cp.async.cg.shared.global [%0], [%1], 16;" :: "r"(dst), "l"(src))
#define CP_COMMIT() asm volatile("cp.async.commit_group;")
#define CP_WAIT1()  asm volatile("cp.async.wait_group 1;" ::: "memory")

// ---------------- prep 1: T2 (K-major), T2t, Xt (transposed, padded) ----------------
__global__ __launch_bounds__(256) void prep_t2_kernel(const float* __restrict__ x,
                                                      const float* __restrict__ p1w) {
    __shared__ float ts2[64][33];
    __shared__ float tsx[64][33];
    int p0 = blockIdx.x * 32;          // 100 tiles (to 3200)
    int q0 = blockIdx.y * 64;          // 4 tiles over j
    int n  = blockIdx.z;
    int t  = threadIdx.x;
    int tp = t & 31, tq = t >> 5;
    int p = p0 + tp;
    bool pv = (p < HWP);
    const float* xn = x + (long)n * CC * HWP;

#pragma unroll
    for (int qi = 0; qi < 8; qi++) {
        int jl = tq + 8 * qi;
        int j = q0 + jl;
        int jm = (j + 255) & 255;
        float v2 = 0.0f, vx = 0.0f;
        if (pv) {
            v2 = rna_tf32(p1w[jm * HWP + p] * xn[jm * HWP + p]);
            vx = rna_tf32(xn[j * HWP + p]);
            g_T2[((long)n * CC + j) * HWP + p] = v2;
        }
        ts2[jl][tp] = v2;
        tsx[jl][tp] = vx;
    }
    __syncthreads();

    int ql = t & 63, pl = t >> 6;
    float* d2 = g_T2t + ((long)n * PPAD) * CC;
    float* dx = g_Xt  + ((long)n * PPAD) * CC;
#pragma unroll
    for (int pi = 0; pi < 8; pi++) {
        int prow = p0 + pl + 4 * pi;
        d2[(long)prow * CC + q0 + ql] = ts2[ql][pl + 4 * pi];
        dx[(long)prow * CC + q0 + ql] = tsx[ql][pl + 4 * pi];
    }
}

// ---------------- prep 2: A1 = stacked shifted x ----------------
// A1[n][k*256+i][h*56+w'] = x[n,i,h,w'-k+3] if 0<=w'-k+3<56 else 0
__global__ void prep_a1_kernel(const float* __restrict__ x) {
    long idx = (long)blockIdx.x * blockDim.x + threadIdx.x;
    if (idx >= (long)NB * CKD * HWP) return;
    int p = (int)(idx % HWP);
    long t = idx / HWP;
    int row = (int)(t % CKD);
    int n = (int)(t / CKD);
    int k = row >> 8, i = row & 255;
    int h = p / WWd, w = p % WWd;
    int ws = w - k + 3;
    float v = 0.0f;
    if (ws >= 0 && ws < WWd)
        v = rna_tf32(x[((long)n * CC + i) * HWP + h * WWd + ws]);
    g_A1[idx] = v;
}

// ---------------- TF32 mma.sync GEMM (NT): C[m,nn] = sum_k A[m,k]*B[nn,k] ----------------
// CTA 256 thr, block 128x128xBK32, 8 warps (2m x 4n), warp 64x32 = 4x4 m16n8k8.
// ldmatrix.b16 tf32 fragment loads; 3 stages x 32KB -> 2 CTAs/SM.
__global__ __launch_bounds__(256, 2)
void gemm_mma(const float* __restrict__ A, const float* __restrict__ B, float* __restrict__ C,
              int lda, int ldb, int ldc, int KT, int nsplit,
              long sAz, long sBz, long sCz, long spA, long spB, long spC) {
    extern __shared__ __align__(1024) char smem[];
    const uint32_t STGB = 32768;
    uint32_t sb = smem_u32(smem);

    int tid = threadIdx.x, lane = tid & 31, wid = tid >> 5;
    int g = lane >> 2, t = lane & 3;
    int mwarp = (wid & 1) * 64, nwarp = (wid >> 1) * 32;

    int n = blockIdx.z / nsplit, s = blockIdx.z % nsplit;
    const float* Ab = A + (long)n * sAz + (long)s * spA + (long)(blockIdx.x * 128) * lda;
    const float* Bb = B + (long)n * sBz + (long)s * spB + (long)(blockIdx.y * 128) * ldb;

    // staging: threads 0-127 stage A rows, 128-255 stage B rows
    int srow = tid & 127;
    const char* src = (const char*)((tid < 128) ? (Ab + (long)srow * lda)
                                                : (Bb + (long)srow * ldb));
    uint32_t dst = sb + ((tid < 128) ? 0u : 16384u) + (uint32_t)srow * 128;
    uint32_t swz = (srow & 7) * 16;

    // ldmatrix lane bases
    uint32_t aRow[4], aSwz[4];
#pragma unroll
    for (int mi = 0; mi < 4; mi++) {
        int m = mwarp + mi * 16 + (lane & 15);
        aRow[mi] = (uint32_t)(m * 128);
        aSwz[mi] = (uint32_t)((m & 7) << 4);
    }
    uint32_t aKbit = (uint32_t)((lane >> 4) << 4);
    uint32_t bRow[4], bSwz[4];
#pragma unroll
    for (int ni = 0; ni < 4; ni++) {
        int nn = nwarp + ni * 8 + (lane & 7);
        bRow[ni] = (uint32_t)(16384 + nn * 128);
        bSwz[ni] = (uint32_t)((nn & 7) << 4);
    }
    uint32_t bKbit = (uint32_t)(((lane >> 3) & 1) << 4);

    float c[4][4][4];
#pragma unroll
    for (int mi = 0; mi < 4; mi++)
#pragma unroll
        for (int ni = 0; ni < 4; ni++)
#pragma unroll
            for (int e = 0; e < 4; e++) c[mi][ni][e] = 0.0f;

#pragma unroll
    for (int st = 0; st < 2; st++) {
        uint32_t so = st * STGB;
        long go = (long)st * 128;
#pragma unroll
        for (int j = 0; j < 8; j++)
            CP_ASYNC16(dst + so + (uint32_t)((j * 16) ^ swz), src + go + j * 16);
        CP_COMMIT();
    }

    int buf = 0;
#pragma unroll 1
    for (int kt = 0; kt < KT; kt++) {
        CP_WAIT1();
        __syncthreads();
        if (kt + 2 < KT) {
            int b2 = buf + 2; if (b2 >= 3) b2 -= 3;
            uint32_t so = (uint32_t)b2 * STGB;
            long go = (long)(kt + 2) * 128;
#pragma unroll
            for (int j = 0; j < 8; j++)
                CP_ASYNC16(dst + so + (uint32_t)((j * 16) ^ swz), src + go + j * 16);
        }
        CP_COMMIT();

        uint32_t stg = sb + (uint32_t)buf * STGB;
#pragma unroll
        for (int kk = 0; kk < 4; kk++) {
            uint32_t akOff = (uint32_t)(kk * 32) + aKbit;
            uint32_t bkOff = (uint32_t)(kk * 32) + bKbit;
            uint32_t a[4][4];
#pragma unroll
            for (int mi = 0; mi < 4; mi++) {
                uint32_t addr = stg + aRow[mi] + (akOff ^ aSwz[mi]);
                asm volatile(
                    "ldmatrix.sync.aligned.m8n8.x4.shared.b16 {%0,%1,%2,%3}, [%4];"
                    : "=r"(a[mi][0]), "=r"(a[mi][1]), "=r"(a[mi][2]), "=r"(a[mi][3])
                    : "r"(addr));
            }
            uint32_t b[4][2];
#pragma unroll
            for (int ni = 0; ni < 4; ni++) {
                uint32_t addr = stg + bRow[ni] + (bkOff ^ bSwz[ni]);
                asm volatile(
                    "ldmatrix.sync.aligned.m8n8.x2.shared.b16 {%0,%1}, [%2];"
                    : "=r"(b[ni][0]), "=r"(b[ni][1])
                    : "r"(addr));
            }
#pragma unroll
            for (int mi = 0; mi < 4; mi++)
#pragma unroll
                for (int ni = 0; ni < 4; ni++) {
                    asm volatile(
                        "mma.sync.aligned.m16n8k8.row.col.f32.tf32.tf32.f32 "
                        "{%0,%1,%2,%3}, {%4,%5,%6,%7}, {%8,%9}, {%0,%1,%2,%3};"
                        : "+f"(c[mi][ni][0]), "+f"(c[mi][ni][1]),
                          "+f"(c[mi][ni][2]), "+f"(c[mi][ni][3])
                        : "r"(a[mi][0]), "r"(a[mi][1]), "r"(a[mi][2]), "r"(a[mi][3]),
                          "r"(b[ni][0]), "r"(b[ni][1]));
                }
        }
        buf++; if (buf >= 3) buf = 0;
    }

    float* Cz = C + (long)n * sCz + (long)s * spC;
    int colbase = blockIdx.y * 128 + nwarp;
#pragma unroll
    for (int mi = 0; mi < 4; mi++) {
        int row0 = blockIdx.x * 128 + mwarp + mi * 16 + g;
        int row1 = row0 + 8;
#pragma unroll
        for (int ni = 0; ni < 4; ni++) {
            int col = colbase + ni * 8 + 2 * t;
            *(float2*)(Cz + (long)row0 * ldc + col) = make_float2(c[mi][ni][0], c[mi][ni][1]);
            *(float2*)(Cz + (long)row1 * ldc + col) = make_float2(c[mi][ni][2], c[mi][ni][3]);
        }
    }
}

// ---------------- t7 build: A2[(k,i),j] = rna((S[(3,i),(j+1)%256]-S[(k,i),j])/56); U = rna(sum_k) ----------------
__global__ __launch_bounds__(256) void t7_build_kernel() {
    int j = threadIdx.x;
    int i = blockIdx.x;
    int n = blockIdx.y;
    const long H = (long)NB * CKD * CC;
    const float* S0 = g_S + (long)n * CKD * CC;
    const float* S1 = S0 + H;
    int jp1 = (j + 1) & 255;
    long gidx = (long)(3 * 256 + i) * 256 + jp1;
    float Sg = S0[gidx] + S1[gidx];
    float acc = 0.0f;
    float* A2n = g_A2 + (long)n * CKD * CC;
#pragma unroll
    for (int k = 0; k < K7; k++) {
        long sidx = (long)(k * 256 + i) * 256 + j;
        float Sk = S0[sidx] + S1[sidx];
        float t7 = (Sg - Sk) * (1.0f / 56.0f);
        A2n[sidx] = rna_tf32(t7);
        acc += t7;
    }
    g_U[((long)n * CC + i) * CC + j] = rna_tf32(acc);
}

// ---------------- combine: out = s2 * (O1 + sum_k W[(k,i), shifted(p)]) ----------------
__global__ __launch_bounds__(256) void combine_kernel(float* __restrict__ out) {
    int p = blockIdx.x * 256 + threadIdx.x;
    if (p >= HWP) return;
    int i = blockIdx.y;
    int n = blockIdx.z;
    int h = p / WWd, w = p % WWd;
    int h1 = (h + HH - 1) % HH;
    int u = (w + 1) % WWd;
    const float* Wn = g_W + (long)n * CKD * PPAD;
    float acc = g_O1[((long)n * CC + i) * PPAD + p];
    long base = (long)i * PPAD + h1 * WWd + u - 3;   // k=0 term at +0, stride per k = 256*PPAD+1
#pragma unroll
    for (int k = 0; k < K7; k++) {
        int wv = u + k - 3;
        if (wv >= 0 && wv < WWd)
            acc += Wn[base + (long)k * (256 * PPAD + 1)];
    }
    out[((long)n * CC + i) * HWP + p] = acc * 0.0236227795f;  // 1/sqrt(1792)
}

// ---------------- launch ----------------
extern "C" void kernel_launch(void* const* d_in, const int* in_sizes, int n_in,
                              void* d_out, int out_size) {
    (void)in_sizes; (void)n_in; (void)out_size;
    const float* x   = (const float*)d_in[0];
    const float* p1w = (const float*)d_in[1];
    float* out = (float*)d_out;

    const int SMEM = 3 * 32768;  // 96 KB -> 2 CTAs/SM
    cudaFuncSetAttribute(gemm_mma, cudaFuncAttributeMaxDynamicSharedMemorySize, SMEM);

    prep_t2_kernel<<<dim3(PPAD / 32, CC / 64, NB), 256>>>(x, p1w);
    {
        long total = (long)NB * CKD * HWP;
        prep_a1_kernel<<<(int)((total + 255) / 256), 256>>>(x);
    }

    float *A1, *T2, *T2t, *Xt, *S, *A2, *U, *W, *O1;
    cudaGetSymbolAddress((void**)&A1,  g_A1);
    cudaGetSymbolAddress((void**)&T2,  g_T2);
    cudaGetSymbolAddress((void**)&T2t, g_T2t);
    cudaGetSymbolAddress((void**)&Xt,  g_Xt);
    cudaGetSymbolAddress((void**)&S,   g_S);
    cudaGetSymbolAddress((void**)&A2,  g_A2);
    cudaGetSymbolAddress((void**)&U,   g_U);
    cudaGetSymbolAddress((void**)&W,   g_W);
    cudaGetSymbolAddress((void**)&O1,  g_O1);

    // GEMM-A (split-K2): S[s][n][(k,i)][j] = sum_p A1[(k,i),p] * T2[j,p]
    // M=1792, N=256, K=1568 per split
    gemm_mma<<<dim3(CKD / 128, CC / 128, NB * 2), 256, SMEM>>>(
        A1, T2, S,
        HWP, HWP, CC, /*KT=*/1568 / 32, /*nsplit=*/2,
        (long)CKD * HWP, (long)CC * HWP, (long)CKD * CC,
        /*spA=*/1568, /*spB=*/1568, /*spC=*/(long)NB * CKD * CC);

    t7_build_kernel<<<dim3(CC, NB), 256>>>();

    // GEMM-B: W[(k,i), p'] = sum_j A2[(k,i),j] * T2t[p',j];  M=1792, N=3200, K=256
    gemm_mma<<<dim3(CKD / 128, PPAD / 128, NB), 256, SMEM>>>(
        A2, T2t, W,
        CC, CC, PPAD, /*KT=*/CC / 32, /*nsplit=*/1,
        (long)CKD * CC, (long)PPAD * CC, (long)CKD * PPAD,
        0, 0, 0);

    // GEMM-C: O1[i, p] = sum_j U[i,j] * Xt[p,j];  M=256, N=3200, K=256
    gemm_mma<<<dim3(CC / 128, PPAD / 128, NB), 256, SMEM>>>(
        U, Xt, O1,
        CC, CC, PPAD, /*KT=*/CC / 32, /*nsplit=*/1,
        (long)CC * CC, (long)PPAD * CC, (long)CC * PPAD,
        0, 0, 0);

    combine_kernel<<<dim3((HWP + 255) / 256, CC, NB), 256>>>(out);
}

// round 12
// speedup vs baseline: 1.7237x; 1.5486x over previous
#include <cuda_runtime.h>
#include <cuda_fp16.h>
#include <cstdint>

#define NB    8
#define CC    256
#define HH    56
#define WWd   56
#define HWP   3136
#define PPAD  3200
#define K7    7
#define CKD   1792     // 7*256
#define KPADA 3200     // padded K for GEMM-A (64-aligned split halves)

// ---------------- scratch ----------------
__device__ __half g_A1 [NB * CKD * KPADA];  //  92 MB: stacked shifted x (fp16), K=p padded
__device__ __half g_T2 [NB * CC  * KPADA];  //  13 MB: t2[j,p] K-major padded
__device__ __half g_T2t[NB * PPAD * CC];    //  13 MB: t2^T [p,j]
__device__ __half g_Xt [NB * PPAD * CC];    //  13 MB: x^T  [p,j]
__device__ float  g_S  [2 * NB * CKD * CC]; //  29 MB: GEMM-A split-K partials (f32)
__device__ __half g_A2 [NB * CKD * CC];     //   7 MB: t7 rows (k*256+i), K=j (fp16)
__device__ __half g_U  [NB * CC * CC];      //   1 MB: sum_k t7 (fp16)
__device__ float  g_W  [NB * CKD * PPAD];   // 184 MB: GEMM-B out (f32)
__device__ float  g_O1 [NB * CC * PPAD];    //  26 MB: U*x (f32)

__device__ __forceinline__ uint32_t smem_u32(const void* p) {
    uint32_t a;
    asm("{ .reg .u64 t; cvta.to.shared.u64 t, %1; cvt.u32.u64 %0, t; }" : "=r"(a) : "l"(p));
    return a;
}
#define CP_ASYNC16(dst, src) \
    asm volatile("cp.async.cg.shared.global [%0], [%1], 16;" :: "r"(dst), "l"(src))
#define CP_COMMIT() asm volatile("cp.async.commit_group;")
#define CP_WAIT1()  asm volatile("cp.async.wait_group 1;" ::: "memory")

// ---------------- prep 1: T2 (K-major padded), T2t, Xt ----------------
__global__ __launch_bounds__(256) void prep_t2_kernel(const float* __restrict__ x,
                                                      const float* __restrict__ p1w) {
    __shared__ __half ts2[64][40];
    __shared__ __half tsx[64][40];
    int p0 = blockIdx.x * 32;          // 100 tiles (to 3200)
    int q0 = blockIdx.y * 64;          // 4 tiles over j
    int n  = blockIdx.z;
    int t  = threadIdx.x;
    int tp = t & 31, tq = t >> 5;
    int p = p0 + tp;
    bool pv = (p < HWP);
    const float* xn = x + (long)n * CC * HWP;

#pragma unroll
    for (int qi = 0; qi < 8; qi++) {
        int jl = tq + 8 * qi;
        int j = q0 + jl;
        int jm = (j + 255) & 255;
        __half v2 = __float2half_rn(0.0f), vx = v2;
        if (pv) {
            v2 = __float2half_rn(p1w[jm * HWP + p] * xn[jm * HWP + p]);
            vx = __float2half_rn(xn[j * HWP + p]);
        }
        g_T2[((long)n * CC + j) * KPADA + p] = v2;   // pad region gets zeros
        ts2[jl][tp] = v2;
        tsx[jl][tp] = vx;
    }
    __syncthreads();

    int ql = t & 63, pl = t >> 6;
    __half* d2 = g_T2t + ((long)n * PPAD) * CC;
    __half* dx = g_Xt  + ((long)n * PPAD) * CC;
#pragma unroll
    for (int pi = 0; pi < 8; pi++) {
        int prow = p0 + pl + 4 * pi;
        d2[(long)prow * CC + q0 + ql] = ts2[ql][pl + 4 * pi];
        dx[(long)prow * CC + q0 + ql] = tsx[ql][pl + 4 * pi];
    }
}

// ---------------- prep 2: A1 = stacked shifted x (fp16, padded K) ----------------
__global__ void prep_a1_kernel(const float* __restrict__ x) {
    long idx = (long)blockIdx.x * blockDim.x + threadIdx.x;
    if (idx >= (long)NB * CKD * KPADA) return;
    int p = (int)(idx % KPADA);
    long t = idx / KPADA;
    int row = (int)(t % CKD);
    int n = (int)(t / CKD);
    int k = row >> 8, i = row & 255;
    int h = p / WWd, w = p % WWd;
    int ws = w - k + 3;
    float v = 0.0f;
    if (p < HWP && ws >= 0 && ws < WWd)
        v = x[((long)n * CC + i) * HWP + h * WWd + ws];
    g_A1[idx] = __float2half_rn(v);
}

// ---------------- fp16 mma.sync GEMM (NT): C[m,nn] = sum_k A[m,k]*B[nn,k] ----------------
// CTA 256 thr, block 128x128xBK64(fp16), 8 warps (2m x 4n), warp 64x32 = 4x4 m16n8k16.
// Same 128B/row staging + swizzle as tf32 version; ldmatrix addressing identical.
__global__ __launch_bounds__(256, 2)
void gemm_mma(const __half* __restrict__ A, const __half* __restrict__ B, float* __restrict__ C,
              int lda, int ldb, int ldc, int KT, int nsplit,
              long sAz, long sBz, long sCz, long spA, long spB, long spC) {
    extern __shared__ __align__(1024) char smem[];
    const uint32_t STGB = 32768;
    uint32_t sb = smem_u32(smem);

    int tid = threadIdx.x, lane = tid & 31, wid = tid >> 5;
    int g = lane >> 2, t = lane & 3;
    int mwarp = (wid & 1) * 64, nwarp = (wid >> 1) * 32;

    int n = blockIdx.z / nsplit, s = blockIdx.z % nsplit;
    const __half* Ab = A + (long)n * sAz + (long)s * spA + (long)(blockIdx.x * 128) * lda;
    const __half* Bb = B + (long)n * sBz + (long)s * spB + (long)(blockIdx.y * 128) * ldb;

    // staging: threads 0-127 stage A rows, 128-255 stage B rows (128B = 64 fp16 per row/stage)
    int srow = tid & 127;
    const char* src = (const char*)((tid < 128) ? (Ab + (long)srow * lda)
                                                : (Bb + (long)srow * ldb));
    uint32_t dst = sb + ((tid < 128) ? 0u : 16384u) + (uint32_t)srow * 128;
    uint32_t swz = (srow & 7) * 16;

    // ldmatrix lane bases (same addressing as tf32 trick; granule = 32B = 16 fp16)
    uint32_t aRow[4], aSwz[4];
#pragma unroll
    for (int mi = 0; mi < 4; mi++) {
        int m = mwarp + mi * 16 + (lane & 15);
        aRow[mi] = (uint32_t)(m * 128);
        aSwz[mi] = (uint32_t)((m & 7) << 4);
    }
    uint32_t aKbit = (uint32_t)((lane >> 4) << 4);
    uint32_t bRow[4], bSwz[4];
#pragma unroll
    for (int ni = 0; ni < 4; ni++) {
        int nn = nwarp + ni * 8 + (lane & 7);
        bRow[ni] = (uint32_t)(16384 + nn * 128);
        bSwz[ni] = (uint32_t)((nn & 7) << 4);
    }
    uint32_t bKbit = (uint32_t)(((lane >> 3) & 1) << 4);

    float c[4][4][4];
#pragma unroll
    for (int mi = 0; mi < 4; mi++)
#pragma unroll
        for (int ni = 0; ni < 4; ni++)
#pragma unroll
            for (int e = 0; e < 4; e++) c[mi][ni][e] = 0.0f;

#pragma unroll
    for (int st = 0; st < 2; st++) {
        uint32_t so = st * STGB;
        long go = (long)st * 128;
#pragma unroll
        for (int j = 0; j < 8; j++)
            CP_ASYNC16(dst + so + (uint32_t)((j * 16) ^ swz), src + go + j * 16);
        CP_COMMIT();
    }

    int buf = 0;
#pragma unroll 1
    for (int kt = 0; kt < KT; kt++) {
        CP_WAIT1();
        __syncthreads();
        if (kt + 2 < KT) {
            int b2 = buf + 2; if (b2 >= 3) b2 -= 3;
            uint32_t so = (uint32_t)b2 * STGB;
            long go = (long)(kt + 2) * 128;
#pragma unroll
            for (int j = 0; j < 8; j++)
                CP_ASYNC16(dst + so + (uint32_t)((j * 16) ^ swz), src + go + j * 16);
        }
        CP_COMMIT();

        uint32_t stg = sb + (uint32_t)buf * STGB;
#pragma unroll
        for (int kk = 0; kk < 4; kk++) {      // 4 x k16 fp16 = 64 elems per chunk
            uint32_t akOff = (uint32_t)(kk * 32) + aKbit;
            uint32_t bkOff = (uint32_t)(kk * 32) + bKbit;
            uint32_t a[4][4];
#pragma unroll
            for (int mi = 0; mi < 4; mi++) {
                uint32_t addr = stg + aRow[mi] + (akOff ^ aSwz[mi]);
                asm volatile(
                    "ldmatrix.sync.aligned.m8n8.x4.shared.b16 {%0,%1,%2,%3}, [%4];"
                    : "=r"(a[mi][0]), "=r"(a[mi][1]), "=r"(a[mi][2]), "=r"(a[mi][3])
                    : "r"(addr));
            }
            uint32_t b[4][2];
#pragma unroll
            for (int ni = 0; ni < 4; ni++) {
                uint32_t addr = stg + bRow[ni] + (bkOff ^ bSwz[ni]);
                asm volatile(
                    "ldmatrix.sync.aligned.m8n8.x2.shared.b16 {%0,%1}, [%2];"
                    : "=r"(b[ni][0]), "=r"(b[ni][1])
                    : "r"(addr));
            }
#pragma unroll
            for (int mi = 0; mi < 4; mi++)
#pragma unroll
                for (int ni = 0; ni < 4; ni++) {
                    asm volatile(
                        "mma.sync.aligned.m16n8k16.row.col.f32.f16.f16.f32 "
                        "{%0,%1,%2,%3}, {%4,%5,%6,%7}, {%8,%9}, {%0,%1,%2,%3};"
                        : "+f"(c[mi][ni][0]), "+f"(c[mi][ni][1]),
                          "+f"(c[mi][ni][2]), "+f"(c[mi][ni][3])
                        : "r"(a[mi][0]), "r"(a[mi][1]), "r"(a[mi][2]), "r"(a[mi][3]),
                          "r"(b[ni][0]), "r"(b[ni][1]));
                }
        }
        buf++; if (buf >= 3) buf = 0;
    }

    float* Cz = C + (long)n * sCz + (long)s * spC;
    int colbase = blockIdx.y * 128 + nwarp;
#pragma unroll
    for (int mi = 0; mi < 4; mi++) {
        int row0 = blockIdx.x * 128 + mwarp + mi * 16 + g;
        int row1 = row0 + 8;
#pragma unroll
        for (int ni = 0; ni < 4; ni++) {
            int col = colbase + ni * 8 + 2 * t;
            *(float2*)(Cz + (long)row0 * ldc + col) = make_float2(c[mi][ni][0], c[mi][ni][1]);
            *(float2*)(Cz + (long)row1 * ldc + col) = make_float2(c[mi][ni][2], c[mi][ni][3]);
        }
    }
}

// ---------------- t7 build ----------------
__global__ __launch_bounds__(256) void t7_build_kernel() {
    int j = threadIdx.x;
    int i = blockIdx.x;
    int n = blockIdx.y;
    const long H = (long)NB * CKD * CC;
    const float* S0 = g_S + (long)n * CKD * CC;
    const float* S1 = S0 + H;
    int jp1 = (j + 1) & 255;
    long gidx = (long)(3 * 256 + i) * 256 + jp1;
    float Sg = S0[gidx] + S1[gidx];
    float acc = 0.0f;
    __half* A2n = g_A2 + (long)n * CKD * CC;
#pragma unroll
    for (int k = 0; k < K7; k++) {
        long sidx = (long)(k * 256 + i) * 256 + j;
        float Sk = S0[sidx] + S1[sidx];
        float t7 = (Sg - Sk) * (1.0f / 56.0f);
        A2n[sidx] = __float2half_rn(t7);
        acc += t7;
    }
    g_U[((long)n * CC + i) * CC + j] = __float2half_rn(acc);
}

// ---------------- combine ----------------
__global__ __launch_bounds__(256) void combine_kernel(float* __restrict__ out) {
    int p = blockIdx.x * 256 + threadIdx.x;
    if (p >= HWP) return;
    int i = blockIdx.y;
    int n = blockIdx.z;
    int h = p / WWd, w = p % WWd;
    int h1 = (h + HH - 1) % HH;
    int u = (w + 1) % WWd;
    const float* Wn = g_W + (long)n * CKD * PPAD;
    float acc = g_O1[((long)n * CC + i) * PPAD + p];
    long base = (long)i * PPAD + h1 * WWd + u - 3;
#pragma unroll
    for (int k = 0; k < K7; k++) {
        int wv = u + k - 3;
        if (wv >= 0 && wv < WWd)
            acc += Wn[base + (long)k * (256 * PPAD + 1)];
    }
    out[((long)n * CC + i) * HWP + p] = acc * 0.0236227795f;  // 1/sqrt(1792)
}

// ---------------- launch ----------------
extern "C" void kernel_launch(void* const* d_in, const int* in_sizes, int n_in,
                              void* d_out, int out_size) {
    (void)in_sizes; (void)n_in; (void)out_size;
    const float* x   = (const float*)d_in[0];
    const float* p1w = (const float*)d_in[1];
    float* out = (float*)d_out;

    const int SMEM = 3 * 32768;  // 96 KB -> 2 CTAs/SM
    cudaFuncSetAttribute(gemm_mma, cudaFuncAttributeMaxDynamicSharedMemorySize, SMEM);

    prep_t2_kernel<<<dim3(KPADA / 32, CC / 64, NB), 256>>>(x, p1w);
    {
        long total = (long)NB * CKD * KPADA;
        prep_a1_kernel<<<(int)((total + 255) / 256), 256>>>(x);
    }

    __half *A1, *T2, *T2t, *Xt, *A2, *U;
    float *S, *W, *O1;
    cudaGetSymbolAddress((void**)&A1,  g_A1);
    cudaGetSymbolAddress((void**)&T2,  g_T2);
    cudaGetSymbolAddress((void**)&T2t, g_T2t);
    cudaGetSymbolAddress((void**)&Xt,  g_Xt);
    cudaGetSymbolAddress((void**)&S,   g_S);
    cudaGetSymbolAddress((void**)&A2,  g_A2);
    cudaGetSymbolAddress((void**)&U,   g_U);
    cudaGetSymbolAddress((void**)&W,   g_W);
    cudaGetSymbolAddress((void**)&O1,  g_O1);

    // GEMM-A (split-K2): S[s][n][(k,i)][j] = sum_p A1[(k,i),p]*T2[j,p]
    // M=1792, N=256, K=1600 per split (padded), KT=25
    gemm_mma<<<dim3(CKD / 128, CC / 128, NB * 2), 256, SMEM>>>(
        A1, T2, S,
        KPADA, KPADA, CC, /*KT=*/1600 / 64, /*nsplit=*/2,
        (long)CKD * KPADA, (long)CC * KPADA, (long)CKD * CC,
        /*spA=*/1600, /*spB=*/1600, /*spC=*/(long)NB * CKD * CC);

    t7_build_kernel<<<dim3(CC, NB), 256>>>();

    // GEMM-B: W[(k,i), p'] = sum_j A2[(k,i),j]*T2t[p',j];  M=1792, N=3200, K=256, KT=4
    gemm_mma<<<dim3(CKD / 128, PPAD / 128, NB), 256, SMEM>>>(
        A2, T2t, W,
        CC, CC, PPAD, /*KT=*/CC / 64, /*nsplit=*/1,
        (long)CKD * CC, (long)PPAD * CC, (long)CKD * PPAD,
        0, 0, 0);

    // GEMM-C: O1[i, p] = sum_j U[i,j]*Xt[p,j];  M=256, N=3200, K=256, KT=4
    gemm_mma<<<dim3(CC / 128, PPAD / 128, NB), 256, SMEM>>>(
        U, Xt, O1,
        CC, CC, PPAD, /*KT=*/CC / 64, /*nsplit=*/1,
        (long)CC * CC, (long)PPAD * CC, (long)CC * PPAD,
        0, 0, 0);

    combine_kernel<<<dim3((HWP + 255) / 256, CC, NB), 256>>>(out);
}

// round 13
// speedup vs baseline: 1.9930x; 1.1563x over previous
#include <cuda_runtime.h>
#include <cuda_fp16.h>
#include <cstdint>

#define NB    8
#define CC    256
#define HH    56
#define WWd   56
#define HWP   3136
#define PPAD  3200
#define K7    7
#define CKD   1792     // 7*256
#define KPADA 3200     // padded K for GEMM-A

// ---------------- scratch ----------------
__device__ __half g_A1 [NB * CKD * KPADA];  //  92 MB: stacked shifted x (fp16)
__device__ __half g_T2 [NB * CC  * KPADA];  //  13 MB: t2[j,p] K-major padded
__device__ __half g_T2t[NB * PPAD * CC];    //  13 MB: t2^T [p,j]
__device__ __half g_Xt [NB * PPAD * CC];    //  13 MB: x^T  [p,j]
__device__ float  g_S  [2 * NB * CKD * CC]; //  29 MB: GEMM-A split-K partials (f32)
__device__ __half g_A2 [NB * CKD * CC];     //   7 MB: t7 (fp16)
__device__ __half g_U  [NB * CC * CC];      //   1 MB: sum_k t7 (fp16)
__device__ __half g_W  [NB * CKD * PPAD];   //  92 MB: GEMM-B out (fp16)
__device__ __half g_O1 [NB * CC * PPAD];    //  13 MB: U*x (fp16)

__device__ __forceinline__ uint32_t smem_u32(const void* p) {
    uint32_t a;
    asm("{ .reg .u64 t; cvta.to.shared.u64 t, %1; cvt.u32.u64 %0, t; }" : "=r"(a) : "l"(p));
    return a;
}
#define CP_ASYNC16(dst, src) \
    asm volatile("cp.async.cg.shared.global [%0], [%1], 16;" :: "r"(dst), "l"(src))
#define CP_COMMIT() asm volatile("cp.async.commit_group;")
#define CP_WAIT1()  asm volatile("cp.async.wait_group 1;" ::: "memory")

// ---------------- prep 1: T2 (K-major padded), T2t, Xt ----------------
__global__ __launch_bounds__(256) void prep_t2_kernel(const float* __restrict__ x,
                                                      const float* __restrict__ p1w) {
    __shared__ __half ts2[64][40];
    __shared__ __half tsx[64][40];
    int p0 = blockIdx.x * 32;
    int q0 = blockIdx.y * 64;
    int n  = blockIdx.z;
    int t  = threadIdx.x;
    int tp = t & 31, tq = t >> 5;
    int p = p0 + tp;
    bool pv = (p < HWP);
    const float* xn = x + (long)n * CC * HWP;

#pragma unroll
    for (int qi = 0; qi < 8; qi++) {
        int jl = tq + 8 * qi;
        int j = q0 + jl;
        int jm = (j + 255) & 255;
        __half v2 = __float2half_rn(0.0f), vx = v2;
        if (pv) {
            v2 = __float2half_rn(p1w[jm * HWP + p] * xn[jm * HWP + p]);
            vx = __float2half_rn(xn[j * HWP + p]);
        }
        g_T2[((long)n * CC + j) * KPADA + p] = v2;
        ts2[jl][tp] = v2;
        tsx[jl][tp] = vx;
    }
    __syncthreads();

    int ql = t & 63, pl = t >> 6;
    __half* d2 = g_T2t + ((long)n * PPAD) * CC;
    __half* dx = g_Xt  + ((long)n * PPAD) * CC;
#pragma unroll
    for (int pi = 0; pi < 8; pi++) {
        int prow = p0 + pl + 4 * pi;
        d2[(long)prow * CC + q0 + ql] = ts2[ql][pl + 4 * pi];
        dx[(long)prow * CC + q0 + ql] = tsx[ql][pl + 4 * pi];
    }
}

// ---------------- prep 2: A1 = stacked shifted x (fp16), 8 elems/thread, 16B stores ----------------
__global__ void prep_a1_kernel(const float* __restrict__ x) {
    long idx = (long)blockIdx.x * blockDim.x + threadIdx.x;
    const int PW = KPADA / 8;   // 400
    if (idx >= (long)NB * CKD * PW) return;
    int p8 = (int)(idx % PW) * 8;
    long t = idx / PW;
    int row = (int)(t % CKD);
    int n = (int)(t / CKD);
    int k = row >> 8, i = row & 255;
    const float* xr = x + ((long)n * CC + i) * HWP;

    int h = p8 / WWd, w = p8 % WWd;
    __half2 buf[4];
#pragma unroll
    for (int e = 0; e < 8; e += 2) {
        float v[2];
#pragma unroll
        for (int d = 0; d < 2; d++) {
            float vv = 0.0f;
            int ws = w - k + 3;
            if (p8 + e + d < HWP && ws >= 0 && ws < WWd)
                vv = xr[h * WWd + ws];
            v[d] = vv;
            if (++w == WWd) { w = 0; h++; }
        }
        buf[e >> 1] = __floats2half2_rn(v[0], v[1]);
    }
    *(uint4*)&g_A1[t * KPADA + p8] = *(uint4*)buf;
}

// ---------------- fp16 mma.sync GEMM (NT): C[m,nn] = sum_k A[m,k]*B[nn,k] ----------------
// CTA 256 thr, block 128x128xBK64, 8 warps (2m x 4n), warp 64x32 = 4x4 m16n8k16.
// half_out: 0 -> f32 output, 1 -> fp16 output.
__global__ __launch_bounds__(256, 2)
void gemm_mma(const __half* __restrict__ A, const __half* __restrict__ B, void* __restrict__ C,
              int lda, int ldb, int ldc, int KT, int nsplit, int half_out,
              long sAz, long sBz, long sCz, long spA, long spB, long spC) {
    extern __shared__ __align__(1024) char smem[];
    const uint32_t STGB = 32768;
    uint32_t sb = smem_u32(smem);

    int tid = threadIdx.x, lane = tid & 31, wid = tid >> 5;
    int g = lane >> 2, t = lane & 3;
    int mwarp = (wid & 1) * 64, nwarp = (wid >> 1) * 32;

    int n = blockIdx.z / nsplit, s = blockIdx.z % nsplit;
    const __half* Ab = A + (long)n * sAz + (long)s * spA + (long)(blockIdx.x * 128) * lda;
    const __half* Bb = B + (long)n * sBz + (long)s * spB + (long)(blockIdx.y * 128) * ldb;

    int srow = tid & 127;
    const char* src = (const char*)((tid < 128) ? (Ab + (long)srow * lda)
                                                : (Bb + (long)srow * ldb));
    uint32_t dst = sb + ((tid < 128) ? 0u : 16384u) + (uint32_t)srow * 128;
    uint32_t swz = (srow & 7) * 16;

    uint32_t aRow[4], aSwz[4];
#pragma unroll
    for (int mi = 0; mi < 4; mi++) {
        int m = mwarp + mi * 16 + (lane & 15);
        aRow[mi] = (uint32_t)(m * 128);
        aSwz[mi] = (uint32_t)((m & 7) << 4);
    }
    uint32_t aKbit = (uint32_t)((lane >> 4) << 4);
    uint32_t bRow[4], bSwz[4];
#pragma unroll
    for (int ni = 0; ni < 4; ni++) {
        int nn = nwarp + ni * 8 + (lane & 7);
        bRow[ni] = (uint32_t)(16384 + nn * 128);
        bSwz[ni] = (uint32_t)((nn & 7) << 4);
    }
    uint32_t bKbit = (uint32_t)(((lane >> 3) & 1) << 4);

    float c[4][4][4];
#pragma unroll
    for (int mi = 0; mi < 4; mi++)
#pragma unroll
        for (int ni = 0; ni < 4; ni++)
#pragma unroll
            for (int e = 0; e < 4; e++) c[mi][ni][e] = 0.0f;

#pragma unroll
    for (int st = 0; st < 2; st++) {
        uint32_t so = st * STGB;
        long go = (long)st * 128;
#pragma unroll
        for (int j = 0; j < 8; j++)
            CP_ASYNC16(dst + so + (uint32_t)((j * 16) ^ swz), src + go + j * 16);
        CP_COMMIT();
    }

    int buf = 0;
#pragma unroll 1
    for (int kt = 0; kt < KT; kt++) {
        CP_WAIT1();
        __syncthreads();
        if (kt + 2 < KT) {
            int b2 = buf + 2; if (b2 >= 3) b2 -= 3;
            uint32_t so = (uint32_t)b2 * STGB;
            long go = (long)(kt + 2) * 128;
#pragma unroll
            for (int j = 0; j < 8; j++)
                CP_ASYNC16(dst + so + (uint32_t)((j * 16) ^ swz), src + go + j * 16);
        }
        CP_COMMIT();

        uint32_t stg = sb + (uint32_t)buf * STGB;
#pragma unroll
        for (int kk = 0; kk < 4; kk++) {
            uint32_t akOff = (uint32_t)(kk * 32) + aKbit;
            uint32_t bkOff = (uint32_t)(kk * 32) + bKbit;
            uint32_t a[4][4];
#pragma unroll
            for (int mi = 0; mi < 4; mi++) {
                uint32_t addr = stg + aRow[mi] + (akOff ^ aSwz[mi]);
                asm volatile(
                    "ldmatrix.sync.aligned.m8n8.x4.shared.b16 {%0,%1,%2,%3}, [%4];"
                    : "=r"(a[mi][0]), "=r"(a[mi][1]), "=r"(a[mi][2]), "=r"(a[mi][3])
                    : "r"(addr));
            }
            uint32_t b[4][2];
#pragma unroll
            for (int ni = 0; ni < 4; ni++) {
                uint32_t addr = stg + bRow[ni] + (bkOff ^ bSwz[ni]);
                asm volatile(
                    "ldmatrix.sync.aligned.m8n8.x2.shared.b16 {%0,%1}, [%2];"
                    : "=r"(b[ni][0]), "=r"(b[ni][1])
                    : "r"(addr));
            }
#pragma unroll
            for (int mi = 0; mi < 4; mi++)
#pragma unroll
                for (int ni = 0; ni < 4; ni++) {
                    asm volatile(
                        "mma.sync.aligned.m16n8k16.row.col.f32.f16.f16.f32 "
                        "{%0,%1,%2,%3}, {%4,%5,%6,%7}, {%8,%9}, {%0,%1,%2,%3};"
                        : "+f"(c[mi][ni][0]), "+f"(c[mi][ni][1]),
                          "+f"(c[mi][ni][2]), "+f"(c[mi][ni][3])
                        : "r"(a[mi][0]), "r"(a[mi][1]), "r"(a[mi][2]), "r"(a[mi][3]),
                          "r"(b[ni][0]), "r"(b[ni][1]));
                }
        }
        buf++; if (buf >= 3) buf = 0;
    }

    int colbase = blockIdx.y * 128 + nwarp;
    if (half_out) {
        __half* Cz = (__half*)C + (long)n * sCz + (long)s * spC;
#pragma unroll
        for (int mi = 0; mi < 4; mi++) {
            int row0 = blockIdx.x * 128 + mwarp + mi * 16 + g;
            int row1 = row0 + 8;
#pragma unroll
            for (int ni = 0; ni < 4; ni++) {
                int col = colbase + ni * 8 + 2 * t;
                *(__half2*)(Cz + (long)row0 * ldc + col) = __floats2half2_rn(c[mi][ni][0], c[mi][ni][1]);
                *(__half2*)(Cz + (long)row1 * ldc + col) = __floats2half2_rn(c[mi][ni][2], c[mi][ni][3]);
            }
        }
    } else {
        float* Cz = (float*)C + (long)n * sCz + (long)s * spC;
#pragma unroll
        for (int mi = 0; mi < 4; mi++) {
            int row0 = blockIdx.x * 128 + mwarp + mi * 16 + g;
            int row1 = row0 + 8;
#pragma unroll
            for (int ni = 0; ni < 4; ni++) {
                int col = colbase + ni * 8 + 2 * t;
                *(float2*)(Cz + (long)row0 * ldc + col) = make_float2(c[mi][ni][0], c[mi][ni][1]);
                *(float2*)(Cz + (long)row1 * ldc + col) = make_float2(c[mi][ni][2], c[mi][ni][3]);
            }
        }
    }
}

// ---------------- t7 build ----------------
__global__ __launch_bounds__(256) void t7_build_kernel() {
    int j = threadIdx.x;
    int i = blockIdx.x;
    int n = blockIdx.y;
    const long H = (long)NB * CKD * CC;
    const float* S0 = g_S + (long)n * CKD * CC;
    const float* S1 = S0 + H;
    int jp1 = (j + 1) & 255;
    long gidx = (long)(3 * 256 + i) * 256 + jp1;
    float Sg = S0[gidx] + S1[gidx];
    float acc = 0.0f;
    __half* A2n = g_A2 + (long)n * CKD * CC;
#pragma unroll
    for (int k = 0; k < K7; k++) {
        long sidx = (long)(k * 256 + i) * 256 + j;
        float Sk = S0[sidx] + S1[sidx];
        float t7 = (Sg - Sk) * (1.0f / 56.0f);
        A2n[sidx] = __float2half_rn(t7);
        acc += t7;
    }
    g_U[((long)n * CC + i) * CC + j] = __float2half_rn(acc);
}

// ---------------- combine ----------------
__global__ __launch_bounds__(256) void combine_kernel(float* __restrict__ out) {
    int p = blockIdx.x * 256 + threadIdx.x;
    if (p >= HWP) return;
    int i = blockIdx.y;
    int n = blockIdx.z;
    int h = p / WWd, w = p % WWd;
    int h1 = (h + HH - 1) % HH;
    int u = (w + 1) % WWd;
    const __half* Wn = g_W + (long)n * CKD * PPAD;
    float acc = __half2float(g_O1[((long)n * CC + i) * PPAD + p]);
    long base = (long)i * PPAD + h1 * WWd + u - 3;
#pragma unroll
    for (int k = 0; k < K7; k++) {
        int wv = u + k - 3;
        if (wv >= 0 && wv < WWd)
            acc += __half2float(Wn[base + (long)k * (256 * PPAD + 1)]);
    }
    out[((long)n * CC + i) * HWP + p] = acc * 0.0236227795f;  // 1/sqrt(1792)
}

// ---------------- launch ----------------
extern "C" void kernel_launch(void* const* d_in, const int* in_sizes, int n_in,
                              void* d_out, int out_size) {
    (void)in_sizes; (void)n_in; (void)out_size;
    const float* x   = (const float*)d_in[0];
    const float* p1w = (const float*)d_in[1];
    float* out = (float*)d_out;

    const int SMEM = 3 * 32768;  // 96 KB -> 2 CTAs/SM
    cudaFuncSetAttribute(gemm_mma, cudaFuncAttributeMaxDynamicSharedMemorySize, SMEM);

    prep_t2_kernel<<<dim3(KPADA / 32, CC / 64, NB), 256>>>(x, p1w);
    {
        long total = (long)NB * CKD * (KPADA / 8);
        prep_a1_kernel<<<(int)((total + 255) / 256), 256>>>(x);
    }

    __half *A1, *T2, *T2t, *Xt, *A2, *U, *W, *O1;
    float *S;
    cudaGetSymbolAddress((void**)&A1,  g_A1);
    cudaGetSymbolAddress((void**)&T2,  g_T2);
    cudaGetSymbolAddress((void**)&T2t, g_T2t);
    cudaGetSymbolAddress((void**)&Xt,  g_Xt);
    cudaGetSymbolAddress((void**)&S,   g_S);
    cudaGetSymbolAddress((void**)&A2,  g_A2);
    cudaGetSymbolAddress((void**)&U,   g_U);
    cudaGetSymbolAddress((void**)&W,   g_W);
    cudaGetSymbolAddress((void**)&O1,  g_O1);

    // GEMM-A (split-K2): S[s][n][(k,i)][j] = sum_p A1[(k,i),p]*T2[j,p]; f32 out
    gemm_mma<<<dim3(CKD / 128, CC / 128, NB * 2), 256, SMEM>>>(
        A1, T2, S,
        KPADA, KPADA, CC, /*KT=*/1600 / 64, /*nsplit=*/2, /*half_out=*/0,
        (long)CKD * KPADA, (long)CC * KPADA, (long)CKD * CC,
        /*spA=*/1600, /*spB=*/1600, /*spC=*/(long)NB * CKD * CC);

    t7_build_kernel<<<dim3(CC, NB), 256>>>();

    // GEMM-B: W[(k,i), p'] = sum_j A2[(k,i),j]*T2t[p',j]; fp16 out
    gemm_mma<<<dim3(CKD / 128, PPAD / 128, NB), 256, SMEM>>>(
        A2, T2t, W,
        CC, CC, PPAD, /*KT=*/CC / 64, /*nsplit=*/1, /*half_out=*/1,
        (long)CKD * CC, (long)PPAD * CC, (long)CKD * PPAD,
        0, 0, 0);

    // GEMM-C: O1[i, p] = sum_j U[i,j]*Xt[p,j]; fp16 out
    gemm_mma<<<dim3(CC / 128, PPAD / 128, NB), 256, SMEM>>>(
        U, Xt, O1,
        CC, CC, PPAD, /*KT=*/CC / 64, /*nsplit=*/1, /*half_out=*/1,
        (long)CC * CC, (long)PPAD * CC, (long)CC * PPAD,
        0, 0, 0);

    combine_kernel<<<dim3((HWP + 255) / 256, CC, NB), 256>>>(out);
}

// round 14
// speedup vs baseline: 1.9934x; 1.0002x over previous
#include <cuda_runtime.h>
#include <cuda_fp16.h>
#include <cstdint>

#define NB    8
#define CC    256
#define HH    56
#define WWd   56
#define HWP   3136
#define PPAD  3200
#define K7    7
#define CKD   1792     // 7*256
#define KA    3136     // exact K for GEMM-A (49 chunks of 64)
#define NSPL  4        // split-K for GEMM-A: 12+12+12+13 chunks
#define SPOFF 768      // elements per regular split (12*64)

// ---------------- scratch ----------------
__device__ __half g_A1 [NB * CKD * KA];     //  90 MB: stacked shifted x (fp16)
__device__ __half g_T2 [NB * CC  * KA];     //  13 MB: t2[j,p] K-major
__device__ __half g_T2t[NB * PPAD * CC];    //  13 MB: t2^T [p,j]
__device__ __half g_Xt [NB * PPAD * CC];    //  13 MB: x^T  [p,j]
__device__ float  g_S  [NSPL * NB * CKD * CC]; // 59 MB: GEMM-A split-K partials (f32)
__device__ __half g_A2 [NB * CKD * CC];     //   7 MB: t7 (fp16)
__device__ __half g_U  [NB * CC * CC];      //   1 MB: sum_k t7 (fp16)
__device__ __half g_W  [NB * CKD * PPAD];   //  92 MB: GEMM-B out (fp16)
__device__ __half g_O1 [NB * CC * PPAD];    //  13 MB: U*x (fp16)

__device__ __forceinline__ uint32_t smem_u32(const void* p) {
    uint32_t a;
    asm("{ .reg .u64 t; cvta.to.shared.u64 t, %1; cvt.u32.u64 %0, t; }" : "=r"(a) : "l"(p));
    return a;
}
#define CP_ASYNC16(dst, src) \
    asm volatile("cp.async.cg.shared.global [%0], [%1], 16;" :: "r"(dst), "l"(src))
#define CP_COMMIT() asm volatile("cp.async.commit_group;")
#define CP_WAIT1()  asm volatile("cp.async.wait_group 1;" ::: "memory")

// ---------------- prep 1: T2 (K-major), T2t, Xt ----------------
__global__ __launch_bounds__(256) void prep_t2_kernel(const float* __restrict__ x,
                                                      const float* __restrict__ p1w) {
    __shared__ __half ts2[64][40];
    __shared__ __half tsx[64][40];
    int p0 = blockIdx.x * 32;          // 100 tiles to 3200 (transpose rows padded)
    int q0 = blockIdx.y * 64;
    int n  = blockIdx.z;
    int t  = threadIdx.x;
    int tp = t & 31, tq = t >> 5;
    int p = p0 + tp;
    bool pv = (p < HWP);
    const float* xn = x + (long)n * CC * HWP;

#pragma unroll
    for (int qi = 0; qi < 8; qi++) {
        int jl = tq + 8 * qi;
        int j = q0 + jl;
        int jm = (j + 255) & 255;
        __half v2 = __float2half_rn(0.0f), vx = v2;
        if (pv) {
            v2 = __float2half_rn(p1w[jm * HWP + p] * xn[jm * HWP + p]);
            vx = __float2half_rn(xn[j * HWP + p]);
            g_T2[((long)n * CC + j) * KA + p] = v2;
        }
        ts2[jl][tp] = v2;
        tsx[jl][tp] = vx;
    }
    __syncthreads();

    int ql = t & 63, pl = t >> 6;
    __half* d2 = g_T2t + ((long)n * PPAD) * CC;
    __half* dx = g_Xt  + ((long)n * PPAD) * CC;
#pragma unroll
    for (int pi = 0; pi < 8; pi++) {
        int prow = p0 + pl + 4 * pi;
        d2[(long)prow * CC + q0 + ql] = ts2[ql][pl + 4 * pi];
        dx[(long)prow * CC + q0 + ql] = tsx[ql][pl + 4 * pi];
    }
}

// ---------------- prep 2: A1 = stacked shifted x (fp16), 8 elems/thread ----------------
__global__ void prep_a1_kernel(const float* __restrict__ x) {
    long idx = (long)blockIdx.x * blockDim.x + threadIdx.x;
    const int PW = KA / 8;   // 392
    if (idx >= (long)NB * CKD * PW) return;
    int p8 = (int)(idx % PW) * 8;
    long t = idx / PW;
    int row = (int)(t % CKD);
    int n = (int)(t / CKD);
    int k = row >> 8, i = row & 255;
    const float* xr = x + ((long)n * CC + i) * HWP;

    int h = p8 / WWd, w = p8 % WWd;
    __half2 buf[4];
#pragma unroll
    for (int e = 0; e < 8; e += 2) {
        float v[2];
#pragma unroll
        for (int d = 0; d < 2; d++) {
            float vv = 0.0f;
            int ws = w - k + 3;
            if (ws >= 0 && ws < WWd)
                vv = xr[h * WWd + ws];
            v[d] = vv;
            if (++w == WWd) { w = 0; h++; }
        }
        buf[e >> 1] = __floats2half2_rn(v[0], v[1]);
    }
    *(uint4*)&g_A1[t * KA + p8] = *(uint4*)buf;
}

// ---------------- shared fp16 mma GEMM body (NT, 128x128 tile, BK=64) ----------------
// Ab/Bb point at tile origins (row stride lda/ldb); C tile origin with ldc.
// Cf != nullptr -> f32 out, else Ch (fp16 out).
__device__ __forceinline__ void gemm_body(const __half* Ab, const __half* Bb,
                                          float* Cf, __half* Ch,
                                          int lda, int ldb, int ldc, int KT, char* smem) {
    const uint32_t STGB = 32768;
    uint32_t sb = smem_u32(smem);

    int tid = threadIdx.x, lane = tid & 31, wid = tid >> 5;
    int g = lane >> 2, t = lane & 3;
    int mwarp = (wid & 1) * 64, nwarp = (wid >> 1) * 32;

    int srow = tid & 127;
    const char* src = (const char*)((tid < 128) ? (Ab + (long)srow * lda)
                                                : (Bb + (long)srow * ldb));
    uint32_t dst = sb + ((tid < 128) ? 0u : 16384u) + (uint32_t)srow * 128;
    uint32_t swz = (srow & 7) * 16;

    uint32_t aRow[4], aSwz[4];
#pragma unroll
    for (int mi = 0; mi < 4; mi++) {
        int m = mwarp + mi * 16 + (lane & 15);
        aRow[mi] = (uint32_t)(m * 128);
        aSwz[mi] = (uint32_t)((m & 7) << 4);
    }
    uint32_t aKbit = (uint32_t)((lane >> 4) << 4);
    uint32_t bRow[4], bSwz[4];
#pragma unroll
    for (int ni = 0; ni < 4; ni++) {
        int nn = nwarp + ni * 8 + (lane & 7);
        bRow[ni] = (uint32_t)(16384 + nn * 128);
        bSwz[ni] = (uint32_t)((nn & 7) << 4);
    }
    uint32_t bKbit = (uint32_t)(((lane >> 3) & 1) << 4);

    float c[4][4][4];
#pragma unroll
    for (int mi = 0; mi < 4; mi++)
#pragma unroll
        for (int ni = 0; ni < 4; ni++)
#pragma unroll
            for (int e = 0; e < 4; e++) c[mi][ni][e] = 0.0f;

#pragma unroll
    for (int st = 0; st < 2; st++) {
        uint32_t so = st * STGB;
        long go = (long)st * 128;
#pragma unroll
        for (int j = 0; j < 8; j++)
            CP_ASYNC16(dst + so + (uint32_t)((j * 16) ^ swz), src + go + j * 16);
        CP_COMMIT();
    }

    int buf = 0;
#pragma unroll 1
    for (int kt = 0; kt < KT; kt++) {
        CP_WAIT1();
        __syncthreads();
        if (kt + 2 < KT) {
            int b2 = buf + 2; if (b2 >= 3) b2 -= 3;
            uint32_t so = (uint32_t)b2 * STGB;
            long go = (long)(kt + 2) * 128;
#pragma unroll
            for (int j = 0; j < 8; j++)
                CP_ASYNC16(dst + so + (uint32_t)((j * 16) ^ swz), src + go + j * 16);
        }
        CP_COMMIT();

        uint32_t stg = sb + (uint32_t)buf * STGB;
#pragma unroll
        for (int kk = 0; kk < 4; kk++) {
            uint32_t akOff = (uint32_t)(kk * 32) + aKbit;
            uint32_t bkOff = (uint32_t)(kk * 32) + bKbit;
            uint32_t a[4][4];
#pragma unroll
            for (int mi = 0; mi < 4; mi++) {
                uint32_t addr = stg + aRow[mi] + (akOff ^ aSwz[mi]);
                asm volatile(
                    "ldmatrix.sync.aligned.m8n8.x4.shared.b16 {%0,%1,%2,%3}, [%4];"
                    : "=r"(a[mi][0]), "=r"(a[mi][1]), "=r"(a[mi][2]), "=r"(a[mi][3])
                    : "r"(addr));
            }
            uint32_t b[4][2];
#pragma unroll
            for (int ni = 0; ni < 4; ni++) {
                uint32_t addr = stg + bRow[ni] + (bkOff ^ bSwz[ni]);
                asm volatile(
                    "ldmatrix.sync.aligned.m8n8.x2.shared.b16 {%0,%1}, [%2];"
                    : "=r"(b[ni][0]), "=r"(b[ni][1])
                    : "r"(addr));
            }
#pragma unroll
            for (int mi = 0; mi < 4; mi++)
#pragma unroll
                for (int ni = 0; ni < 4; ni++) {
                    asm volatile(
                        "mma.sync.aligned.m16n8k16.row.col.f32.f16.f16.f32 "
                        "{%0,%1,%2,%3}, {%4,%5,%6,%7}, {%8,%9}, {%0,%1,%2,%3};"
                        : "+f"(c[mi][ni][0]), "+f"(c[mi][ni][1]),
                          "+f"(c[mi][ni][2]), "+f"(c[mi][ni][3])
                        : "r"(a[mi][0]), "r"(a[mi][1]), "r"(a[mi][2]), "r"(a[mi][3]),
                          "r"(b[ni][0]), "r"(b[ni][1]));
                }
        }
        buf++; if (buf >= 3) buf = 0;
    }

    if (Cf) {
#pragma unroll
        for (int mi = 0; mi < 4; mi++) {
            int row0 = mwarp + mi * 16 + g;
#pragma unroll
            for (int ni = 0; ni < 4; ni++) {
                int col = nwarp + ni * 8 + 2 * t;
                *(float2*)(Cf + (long)row0 * ldc + col) = make_float2(c[mi][ni][0], c[mi][ni][1]);
                *(float2*)(Cf + (long)(row0 + 8) * ldc + col) = make_float2(c[mi][ni][2], c[mi][ni][3]);
            }
        }
    } else {
#pragma unroll
        for (int mi = 0; mi < 4; mi++) {
            int row0 = mwarp + mi * 16 + g;
#pragma unroll
            for (int ni = 0; ni < 4; ni++) {
                int col = nwarp + ni * 8 + 2 * t;
                *(__half2*)(Ch + (long)row0 * ldc + col) = __floats2half2_rn(c[mi][ni][0], c[mi][ni][1]);
                *(__half2*)(Ch + (long)(row0 + 8) * ldc + col) = __floats2half2_rn(c[mi][ni][2], c[mi][ni][3]);
            }
        }
    }
}

// ---------------- GEMM-A: split-K4 (12/12/12/13 chunks), f32 partials ----------------
__global__ __launch_bounds__(256, 2) void gemm_a_kernel() {
    extern __shared__ __align__(1024) char smem[];
    int n = blockIdx.z >> 2, s = blockIdx.z & 3;
    int KT = 12 + (s == 3 ? 1 : 0);
    const __half* Ab = g_A1 + ((long)n * CKD + blockIdx.x * 128) * KA + s * SPOFF;
    const __half* Bb = g_T2 + ((long)n * CC + blockIdx.y * 128) * KA + s * SPOFF;
    float* Cf = g_S + (long)s * NB * CKD * CC + ((long)n * CKD + blockIdx.x * 128) * CC
              + blockIdx.y * 128;
    gemm_body(Ab, Bb, Cf, nullptr, KA, KA, CC, KT, smem);
}

// ---------------- merged GEMM-B + GEMM-C: K=256, fp16 out ----------------
__global__ __launch_bounds__(256, 2) void gemm_bc_kernel() {
    extern __shared__ __align__(1024) char smem[];
    int n = blockIdx.z;
    const __half *Ab, *Bb;
    __half* Ch;
    if (blockIdx.x < CKD / 128) {   // GEMM-B tile
        Ab = g_A2 + ((long)n * CKD + blockIdx.x * 128) * CC;
        Bb = g_T2t + ((long)n * PPAD + blockIdx.y * 128) * CC;
        Ch = g_W + ((long)n * CKD + blockIdx.x * 128) * PPAD + blockIdx.y * 128;
    } else {                         // GEMM-C tile
        int bx = blockIdx.x - CKD / 128;
        Ab = g_U + ((long)n * CC + bx * 128) * CC;
        Bb = g_Xt + ((long)n * PPAD + blockIdx.y * 128) * CC;
        Ch = g_O1 + ((long)n * CC + bx * 128) * PPAD + blockIdx.y * 128;
    }
    gemm_body(Ab, Bb, nullptr, Ch, CC, CC, PPAD, CC / 64, smem);
}

// ---------------- t7 build (sum 4 partials) ----------------
__global__ __launch_bounds__(256) void t7_build_kernel() {
    int j = threadIdx.x;
    int i = blockIdx.x;
    int n = blockIdx.y;
    const long H = (long)NB * CKD * CC;
    const float* Sn = g_S + (long)n * CKD * CC;
    int jp1 = (j + 1) & 255;
    long gidx = (long)(3 * 256 + i) * 256 + jp1;
    float Sg = Sn[gidx] + Sn[gidx + H] + Sn[gidx + 2 * H] + Sn[gidx + 3 * H];
    float acc = 0.0f;
    __half* A2n = g_A2 + (long)n * CKD * CC;
#pragma unroll
    for (int k = 0; k < K7; k++) {
        long sidx = (long)(k * 256 + i) * 256 + j;
        float Sk = Sn[sidx] + Sn[sidx + H] + Sn[sidx + 2 * H] + Sn[sidx + 3 * H];
        float t7 = (Sg - Sk) * (1.0f / 56.0f);
        A2n[sidx] = __float2half_rn(t7);
        acc += t7;
    }
    g_U[((long)n * CC + i) * CC + j] = __float2half_rn(acc);
}

// ---------------- combine ----------------
__global__ __launch_bounds__(256) void combine_kernel(float* __restrict__ out) {
    int p = blockIdx.x * 256 + threadIdx.x;
    if (p >= HWP) return;
    int i = blockIdx.y;
    int n = blockIdx.z;
    int h = p / WWd, w = p % WWd;
    int h1 = (h + HH - 1) % HH;
    int u = (w + 1) % WWd;
    const __half* Wn = g_W + (long)n * CKD * PPAD;
    float acc = __half2float(g_O1[((long)n * CC + i) * PPAD + p]);
    long base = (long)i * PPAD + h1 * WWd + u - 3;
#pragma unroll
    for (int k = 0; k < K7; k++) {
        int wv = u + k - 3;
        if (wv >= 0 && wv < WWd)
            acc += __half2float(Wn[base + (long)k * (256 * PPAD + 1)]);
    }
    out[((long)n * CC + i) * HWP + p] = acc * 0.0236227795f;  // 1/sqrt(1792)
}

// ---------------- launch ----------------
extern "C" void kernel_launch(void* const* d_in, const int* in_sizes, int n_in,
                              void* d_out, int out_size) {
    (void)in_sizes; (void)n_in; (void)out_size;
    const float* x   = (const float*)d_in[0];
    const float* p1w = (const float*)d_in[1];
    float* out = (float*)d_out;

    const int SMEM = 3 * 32768;  // 96 KB -> 2 CTAs/SM
    cudaFuncSetAttribute(gemm_a_kernel,  cudaFuncAttributeMaxDynamicSharedMemorySize, SMEM);
    cudaFuncSetAttribute(gemm_bc_kernel, cudaFuncAttributeMaxDynamicSharedMemorySize, SMEM);

    prep_t2_kernel<<<dim3(PPAD / 32, CC / 64, NB), 256>>>(x, p1w);
    {
        long total = (long)NB * CKD * (KA / 8);
        prep_a1_kernel<<<(int)((total + 255) / 256), 256>>>(x);
    }

    // GEMM-A: 14 x 2 x (8*4) = 896 CTAs ~ 3.03 waves
    gemm_a_kernel<<<dim3(CKD / 128, CC / 128, NB * NSPL), 256, SMEM>>>();

    t7_build_kernel<<<dim3(CC, NB), 256>>>();

    // merged GEMM-B (x<14) + GEMM-C (x>=14): 16 x 25 x 8 = 3200 CTAs ~ 10.8 waves
    gemm_bc_kernel<<<dim3(CKD / 128 + CC / 128, PPAD / 128, NB), 256, SMEM>>>();

    combine_kernel<<<dim3((HWP + 255) / 256, CC, NB), 256>>>(out);
}

// round 17
// speedup vs baseline: 2.1710x; 1.0891x over previous
#include <cuda_runtime.h>
#include <cuda_fp16.h>
#include <cstdint>

#define NB    8
#define CC    256
#define HH    56
#define WWd   56
#define HWP   3136
#define PPAD  3200
#define K7    7
#define CKD   1792     // 7*256
#define KA    3136     // exact K for GEMM-A (49 chunks of 64)
#define NSPL  4        // split-K for GEMM-A: 12+12+12+13 chunks
#define SPOFF 768      // elements per regular split (12*64)

// ---------------- scratch ----------------
__device__ __half g_A1 [NB * CKD * KA];     //  90 MB: stacked shifted x (fp16)
__device__ __half g_T2 [NB * CC  * KA];     //  13 MB: t2[j,p] K-major
__device__ __half g_T2t[NB * PPAD * CC];    //  13 MB: t2^T [p,j]
__device__ __half g_Xt [NB * PPAD * CC];    //  13 MB: x^T  [p,j]
__device__ float  g_S  [NSPL * NB * CKD * CC]; // 59 MB: GEMM-A split-K partials (f32)
__device__ __half g_A2 [NB * CKD * CC];     //   7 MB: t7 (fp16)
__device__ __half g_U  [NB * CC * CC];      //   1 MB: sum_k t7 (fp16)
__device__ __half g_W  [NB * CKD * PPAD];   //  92 MB: GEMM-B out (fp16)
__device__ __half g_O1 [NB * CC * PPAD];    //  13 MB: U*x (fp16)

__device__ __forceinline__ uint32_t smem_u32(const void* p) {
    uint32_t a;
    asm("{ .reg .u64 t; cvta.to.shared.u64 t, %1; cvt.u32.u64 %0, t; }" : "=r"(a) : "l"(p));
    return a;
}
#define CP_ASYNC16(dst, src) \
    asm volatile("cp.async.cg.shared.global [%0], [%1], 16;" :: "r"(dst), "l"(src))
#define CP_COMMIT() asm volatile("cp.async.commit_group;")
#define CP_WAIT1()  asm volatile("cp.async.wait_group 1;" ::: "memory")

// ---------------- prep 1: T2 (K-major), T2t, Xt ----------------
__global__ __launch_bounds__(256) void prep_t2_kernel(const float* __restrict__ x,
                                                      const float* __restrict__ p1w) {
    __shared__ __half ts2[64][40];
    __shared__ __half tsx[64][40];
    int p0 = blockIdx.x * 32;
    int q0 = blockIdx.y * 64;
    int n  = blockIdx.z;
    int t  = threadIdx.x;
    int tp = t & 31, tq = t >> 5;
    int p = p0 + tp;
    bool pv = (p < HWP);
    const float* xn = x + (long)n * CC * HWP;

#pragma unroll
    for (int qi = 0; qi < 8; qi++) {
        int jl = tq + 8 * qi;
        int j = q0 + jl;
        int jm = (j + 255) & 255;
        __half v2 = __float2half_rn(0.0f), vx = v2;
        if (pv) {
            v2 = __float2half_rn(p1w[jm * HWP + p] * xn[jm * HWP + p]);
            vx = __float2half_rn(xn[j * HWP + p]);
            g_T2[((long)n * CC + j) * KA + p] = v2;
        }
        ts2[jl][tp] = v2;
        tsx[jl][tp] = vx;
    }
    __syncthreads();

    int ql = t & 63, pl = t >> 6;
    __half* d2 = g_T2t + ((long)n * PPAD) * CC;
    __half* dx = g_Xt  + ((long)n * PPAD) * CC;
#pragma unroll
    for (int pi = 0; pi < 8; pi++) {
        int prow = p0 + pl + 4 * pi;
        d2[(long)prow * CC + q0 + ql] = ts2[ql][pl + 4 * pi];
        dx[(long)prow * CC + q0 + ql] = tsx[ql][pl + 4 * pi];
    }
}

// ---------------- prep 2: A1 = stacked shifted x (fp16), 8 elems/thread ----------------
__global__ void prep_a1_kernel(const float* __restrict__ x) {
    long idx = (long)blockIdx.x * blockDim.x + threadIdx.x;
    const int PW = KA / 8;   // 392
    if (idx >= (long)NB * CKD * PW) return;
    int p8 = (int)(idx % PW) * 8;
    long t = idx / PW;
    int row = (int)(t % CKD);
    int n = (int)(t / CKD);
    int k = row >> 8, i = row & 255;
    const float* xr = x + ((long)n * CC + i) * HWP;

    int h = p8 / WWd, w = p8 % WWd;
    __half2 buf[4];
#pragma unroll
    for (int e = 0; e < 8; e += 2) {
        float v[2];
#pragma unroll
        for (int d = 0; d < 2; d++) {
            float vv = 0.0f;
            int ws = w - k + 3;
            if (ws >= 0 && ws < WWd)
                vv = xr[h * WWd + ws];
            v[d] = vv;
            if (++w == WWd) { w = 0; h++; }
        }
        buf[e >> 1] = __floats2half2_rn(v[0], v[1]);
    }
    *(uint4*)&g_A1[t * KA + p8] = *(uint4*)buf;
}

// ---------------- GEMM-A body (NT, 128x128 tile, BK=64, 3-stage, f32 out) ----------------
__device__ __forceinline__ void gemm_body_f32(const __half* Ab, const __half* Bb, float* Cf,
                                              int lda, int ldb, int ldc, int KT, char* smem) {
    const uint32_t STGB = 32768;
    uint32_t sb = smem_u32(smem);

    int tid = threadIdx.x, lane = tid & 31, wid = tid >> 5;
    int g = lane >> 2, t = lane & 3;
    int mwarp = (wid & 1) * 64, nwarp = (wid >> 1) * 32;

    int srow = tid & 127;
    const char* src = (const char*)((tid < 128) ? (Ab + (long)srow * lda)
                                                : (Bb + (long)srow * ldb));
    uint32_t dst = sb + ((tid < 128) ? 0u : 16384u) + (uint32_t)srow * 128;
    uint32_t swz = (srow & 7) * 16;

    uint32_t aRow[4], aSwz[4];
#pragma unroll
    for (int mi = 0; mi < 4; mi++) {
        int m = mwarp + mi * 16 + (lane & 15);
        aRow[mi] = (uint32_t)(m * 128);
        aSwz[mi] = (uint32_t)((m & 7) << 4);
    }
    uint32_t aKbit = (uint32_t)((lane >> 4) << 4);
    uint32_t bRow[4], bSwz[4];
#pragma unroll
    for (int ni = 0; ni < 4; ni++) {
        int nn = nwarp + ni * 8 + (lane & 7);
        bRow[ni] = (uint32_t)(16384 + nn * 128);
        bSwz[ni] = (uint32_t)((nn & 7) << 4);
    }
    uint32_t bKbit = (uint32_t)(((lane >> 3) & 1) << 4);

    float c[4][4][4];
#pragma unroll
    for (int mi = 0; mi < 4; mi++)
#pragma unroll
        for (int ni = 0; ni < 4; ni++)
#pragma unroll
            for (int e = 0; e < 4; e++) c[mi][ni][e] = 0.0f;

#pragma unroll
    for (int st = 0; st < 2; st++) {
        uint32_t so = st * STGB;
        long go = (long)st * 128;
#pragma unroll
        for (int j = 0; j < 8; j++)
            CP_ASYNC16(dst + so + (uint32_t)((j * 16) ^ swz), src + go + j * 16);
        CP_COMMIT();
    }

    int buf = 0;
#pragma unroll 1
    for (int kt = 0; kt < KT; kt++) {
        CP_WAIT1();
        __syncthreads();
        if (kt + 2 < KT) {
            int b2 = buf + 2; if (b2 >= 3) b2 -= 3;
            uint32_t so = (uint32_t)b2 * STGB;
            long go = (long)(kt + 2) * 128;
#pragma unroll
            for (int j = 0; j < 8; j++)
                CP_ASYNC16(dst + so + (uint32_t)((j * 16) ^ swz), src + go + j * 16);
        }
        CP_COMMIT();

        uint32_t stg = sb + (uint32_t)buf * STGB;
#pragma unroll
        for (int kk = 0; kk < 4; kk++) {
            uint32_t akOff = (uint32_t)(kk * 32) + aKbit;
            uint32_t bkOff = (uint32_t)(kk * 32) + bKbit;
            uint32_t a[4][4];
#pragma unroll
            for (int mi = 0; mi < 4; mi++) {
                uint32_t addr = stg + aRow[mi] + (akOff ^ aSwz[mi]);
                asm volatile(
                    "ldmatrix.sync.aligned.m8n8.x4.shared.b16 {%0,%1,%2,%3}, [%4];"
                    : "=r"(a[mi][0]), "=r"(a[mi][1]), "=r"(a[mi][2]), "=r"(a[mi][3])
                    : "r"(addr));
            }
            uint32_t b[4][2];
#pragma unroll
            for (int ni = 0; ni < 4; ni++) {
                uint32_t addr = stg + bRow[ni] + (bkOff ^ bSwz[ni]);
                asm volatile(
                    "ldmatrix.sync.aligned.m8n8.x2.shared.b16 {%0,%1}, [%2];"
                    : "=r"(b[ni][0]), "=r"(b[ni][1])
                    : "r"(addr));
            }
#pragma unroll
            for (int mi = 0; mi < 4; mi++)
#pragma unroll
                for (int ni = 0; ni < 4; ni++) {
                    asm volatile(
                        "mma.sync.aligned.m16n8k16.row.col.f32.f16.f16.f32 "
                        "{%0,%1,%2,%3}, {%4,%5,%6,%7}, {%8,%9}, {%0,%1,%2,%3};"
                        : "+f"(c[mi][ni][0]), "+f"(c[mi][ni][1]),
                          "+f"(c[mi][ni][2]), "+f"(c[mi][ni][3])
                        : "r"(a[mi][0]), "r"(a[mi][1]), "r"(a[mi][2]), "r"(a[mi][3]),
                          "r"(b[ni][0]), "r"(b[ni][1]));
                }
        }
        buf++; if (buf >= 3) buf = 0;
    }

#pragma unroll
    for (int mi = 0; mi < 4; mi++) {
        int row0 = mwarp + mi * 16 + g;
#pragma unroll
        for (int ni = 0; ni < 4; ni++) {
            int col = nwarp + ni * 8 + 2 * t;
            *(float2*)(Cf + (long)row0 * ldc + col) = make_float2(c[mi][ni][0], c[mi][ni][1]);
            *(float2*)(Cf + (long)(row0 + 8) * ldc + col) = make_float2(c[mi][ni][2], c[mi][ni][3]);
        }
    }
}

// ---------------- GEMM-A: split-K4 (12/12/12/13 chunks), f32 partials ----------------
__global__ __launch_bounds__(256, 2) void gemm_a_kernel() {
    extern __shared__ __align__(1024) char smem[];
    int n = blockIdx.z >> 2, s = blockIdx.z & 3;
    int KT = 12 + (s == 3 ? 1 : 0);
    const __half* Ab = g_A1 + ((long)n * CKD + blockIdx.x * 128) * KA + s * SPOFF;
    const __half* Bb = g_T2 + ((long)n * CC + blockIdx.y * 128) * KA + s * SPOFF;
    float* Cf = g_S + (long)s * NB * CKD * CC + ((long)n * CKD + blockIdx.x * 128) * CC
              + blockIdx.y * 128;
    gemm_body_f32(Ab, Bb, Cf, KA, KA, CC, KT, smem);
}

// ---------------- GEMM-BC v2: A-resident (64KB), 2 N-tiles per CTA, B double-buffer ----------------
// FIX vs round 15: __syncthreads() AFTER CP_WAIT1 — cp.async completion is per-thread,
// so a barrier must follow the wait before any thread reads other threads' staged data.
__global__ __launch_bounds__(256, 2) void gemm_bc_kernel() {
    extern __shared__ __align__(1024) char smem[];
    uint32_t sb = smem_u32(smem);
    int tid = threadIdx.x, lane = tid & 31, wid = tid >> 5;
    int g = lane >> 2, t = lane & 3;
    int mwarp = (wid & 1) * 64, nwarp = (wid >> 1) * 32;
    int n = blockIdx.z;

    const __half *Ab, *Bb;
    __half* Chbase;
    if (blockIdx.x < CKD / 128) {
        Ab = g_A2 + ((long)n * CKD + blockIdx.x * 128) * CC;
        Bb = g_T2t + (long)n * PPAD * CC;
        Chbase = g_W + ((long)n * CKD + blockIdx.x * 128) * PPAD;
    } else {
        int bx = blockIdx.x - CKD / 128;
        Ab = g_U + ((long)n * CC + bx * 128) * CC;
        Bb = g_Xt + (long)n * PPAD * CC;
        Chbase = g_O1 + ((long)n * CC + bx * 128) * PPAD;
    }
    int t0 = blockIdx.y * 2;                 // first N-tile (of 25)
    int CT = (t0 + 1 < PPAD / 128) ? 8 : 4;  // chunks this CTA

    // stage full A (64KB): thread -> row tid&127, sub-tiles {2*(tid>>7), +1}
    {
        int r = tid & 127;
        int h2 = tid >> 7;
        const char* arow = (const char*)(Ab + (long)r * CC);
        uint32_t swzA = (r & 7) * 16;
#pragma unroll
        for (int st = 0; st < 2; st++) {
            int sub = h2 * 2 + st;
            uint32_t base = sb + (uint32_t)sub * 16384 + (uint32_t)r * 128;
#pragma unroll
            for (int j = 0; j < 8; j++)
                CP_ASYNC16(base + (uint32_t)((j * 16) ^ swzA), arow + sub * 128 + j * 16);
        }
        CP_COMMIT();   // group: A
    }

    // B staging mapping: thread -> row tid>>1, granules (tid&1)*4 + j
    int brow = tid >> 1;
    int bg0 = (tid & 1) * 4;
    uint32_t bswzS = (brow & 7) * 16;
    // issue B chunk 0 (tile t0, kt 0) into buf 0
    {
        const char* bsrc = (const char*)(Bb + (long)(t0 * 128 + brow) * CC);
        uint32_t bbase = sb + 65536u + (uint32_t)brow * 128;
#pragma unroll
        for (int j = 0; j < 4; j++)
            CP_ASYNC16(bbase + (uint32_t)((((bg0 + j) * 16) ^ bswzS)), bsrc + (bg0 + j) * 16);
        CP_COMMIT();   // group: B0
    }

    uint32_t aRow[4], aSwz[4];
#pragma unroll
    for (int mi = 0; mi < 4; mi++) {
        int m = mwarp + mi * 16 + (lane & 15);
        aRow[mi] = (uint32_t)(m * 128);
        aSwz[mi] = (uint32_t)((m & 7) << 4);
    }
    uint32_t aKbit = (uint32_t)((lane >> 4) << 4);
    uint32_t bRow[4], bSwz[4];
#pragma unroll
    for (int ni = 0; ni < 4; ni++) {
        int nn = nwarp + ni * 8 + (lane & 7);
        bRow[ni] = (uint32_t)(nn * 128);
        bSwz[ni] = (uint32_t)((nn & 7) << 4);
    }
    uint32_t bKbit = (uint32_t)(((lane >> 3) & 1) << 4);

    float c[4][4][4];
#pragma unroll
    for (int mi = 0; mi < 4; mi++)
#pragma unroll
        for (int ni = 0; ni < 4; ni++)
#pragma unroll
            for (int e = 0; e < 4; e++) c[mi][ni][e] = 0.0f;

#pragma unroll 1
    for (int cc = 0; cc < CT; cc++) {
        __syncthreads();                     // all consumers of buf (cc+1)&1 are done
        if (cc + 1 < CT) {                   // issue B(cc+1)
            int ty = t0 + ((cc + 1) >> 2), kt = (cc + 1) & 3;
            const char* bsrc = (const char*)(Bb + (long)(ty * 128 + brow) * CC) + kt * 128;
            uint32_t bbase = sb + 65536u + (uint32_t)((cc + 1) & 1) * 16384 + (uint32_t)brow * 128;
#pragma unroll
            for (int j = 0; j < 4; j++)
                CP_ASYNC16(bbase + (uint32_t)((((bg0 + j) * 16) ^ bswzS)), bsrc + (bg0 + j) * 16);
        }
        CP_COMMIT();
        CP_WAIT1();                          // MY B(cc) (and A) granules complete
        __syncthreads();                     // EVERYONE's B(cc)/A granules complete

        uint32_t stgA = sb + (uint32_t)(cc & 3) * 16384;
        uint32_t stgB = sb + 65536u + (uint32_t)(cc & 1) * 16384;
#pragma unroll
        for (int kk = 0; kk < 4; kk++) {
            uint32_t akOff = (uint32_t)(kk * 32) + aKbit;
            uint32_t bkOff = (uint32_t)(kk * 32) + bKbit;
            uint32_t a[4][4];
#pragma unroll
            for (int mi = 0; mi < 4; mi++) {
                uint32_t addr = stgA + aRow[mi] + (akOff ^ aSwz[mi]);
                asm volatile(
                    "ldmatrix.sync.aligned.m8n8.x4.shared.b16 {%0,%1,%2,%3}, [%4];"
                    : "=r"(a[mi][0]), "=r"(a[mi][1]), "=r"(a[mi][2]), "=r"(a[mi][3])
                    : "r"(addr));
            }
            uint32_t b[4][2];
#pragma unroll
            for (int ni = 0; ni < 4; ni++) {
                uint32_t addr = stgB + bRow[ni] + (bkOff ^ bSwz[ni]);
                asm volatile(
                    "ldmatrix.sync.aligned.m8n8.x2.shared.b16 {%0,%1}, [%2];"
                    : "=r"(b[ni][0]), "=r"(b[ni][1])
                    : "r"(addr));
            }
#pragma unroll
            for (int mi = 0; mi < 4; mi++)
#pragma unroll
                for (int ni = 0; ni < 4; ni++) {
                    asm volatile(
                        "mma.sync.aligned.m16n8k16.row.col.f32.f16.f16.f32 "
                        "{%0,%1,%2,%3}, {%4,%5,%6,%7}, {%8,%9}, {%0,%1,%2,%3};"
                        : "+f"(c[mi][ni][0]), "+f"(c[mi][ni][1]),
                          "+f"(c[mi][ni][2]), "+f"(c[mi][ni][3])
                        : "r"(a[mi][0]), "r"(a[mi][1]), "r"(a[mi][2]), "r"(a[mi][3]),
                          "r"(b[ni][0]), "r"(b[ni][1]));
                }
        }

        if ((cc & 3) == 3) {                 // epilogue for finished N-tile
            int ty = t0 + (cc >> 2);
            __half* Ch = Chbase + ty * 128;
#pragma unroll
            for (int mi = 0; mi < 4; mi++) {
                int row0 = mwarp + mi * 16 + g;
#pragma unroll
                for (int ni = 0; ni < 4; ni++) {
                    int col = nwarp + ni * 8 + 2 * t;
                    *(__half2*)(Ch + (long)row0 * PPAD + col) =
                        __floats2half2_rn(c[mi][ni][0], c[mi][ni][1]);
                    *(__half2*)(Ch + (long)(row0 + 8) * PPAD + col) =
                        __floats2half2_rn(c[mi][ni][2], c[mi][ni][3]);
                    c[mi][ni][0] = c[mi][ni][1] = c[mi][ni][2] = c[mi][ni][3] = 0.0f;
                }
            }
        }
    }
}

// ---------------- t7 build (sum 4 partials) ----------------
__global__ __launch_bounds__(256) void t7_build_kernel() {
    int j = threadIdx.x;
    int i = blockIdx.x;
    int n = blockIdx.y;
    const long H = (long)NB * CKD * CC;
    const float* Sn = g_S + (long)n * CKD * CC;
    int jp1 = (j + 1) & 255;
    long gidx = (long)(3 * 256 + i) * 256 + jp1;
    float Sg = Sn[gidx] + Sn[gidx + H] + Sn[gidx + 2 * H] + Sn[gidx + 3 * H];
    float acc = 0.0f;
    __half* A2n = g_A2 + (long)n * CKD * CC;
#pragma unroll
    for (int k = 0; k < K7; k++) {
        long sidx = (long)(k * 256 + i) * 256 + j;
        float Sk = Sn[sidx] + Sn[sidx + H] + Sn[sidx + 2 * H] + Sn[sidx + 3 * H];
        float t7 = (Sg - Sk) * (1.0f / 56.0f);
        A2n[sidx] = __float2half_rn(t7);
        acc += t7;
    }
    g_U[((long)n * CC + i) * CC + j] = __float2half_rn(acc);
}

// ---------------- combine ----------------
__global__ __launch_bounds__(256) void combine_kernel(float* __restrict__ out) {
    int p = blockIdx.x * 256 + threadIdx.x;
    if (p >= HWP) return;
    int i = blockIdx.y;
    int n = blockIdx.z;
    int h = p / WWd, w = p % WWd;
    int h1 = (h + HH - 1) % HH;
    int u = (w + 1) % WWd;
    const __half* Wn = g_W + (long)n * CKD * PPAD;
    float acc = __half2float(g_O1[((long)n * CC + i) * PPAD + p]);
    long base = (long)i * PPAD + h1 * WWd + u - 3;
#pragma unroll
    for (int k = 0; k < K7; k++) {
        int wv = u + k - 3;
        if (wv >= 0 && wv < WWd)
            acc += __half2float(Wn[base + (long)k * (256 * PPAD + 1)]);
    }
    out[((long)n * CC + i) * HWP + p] = acc * 0.0236227795f;  // 1/sqrt(1792)
}

// ---------------- launch ----------------
extern "C" void kernel_launch(void* const* d_in, const int* in_sizes, int n_in,
                              void* d_out, int out_size) {
    (void)in_sizes; (void)n_in; (void)out_size;
    const float* x   = (const float*)d_in[0];
    const float* p1w = (const float*)d_in[1];
    float* out = (float*)d_out;

    const int SMEM_A  = 3 * 32768;   // 96 KB
    const int SMEM_BC = 6 * 16384;   // 96 KB (64KB A-resident + 2x16KB B)
    cudaFuncSetAttribute(gemm_a_kernel,  cudaFuncAttributeMaxDynamicSharedMemorySize, SMEM_A);
    cudaFuncSetAttribute(gemm_bc_kernel, cudaFuncAttributeMaxDynamicSharedMemorySize, SMEM_BC);

    prep_t2_kernel<<<dim3(PPAD / 32, CC / 64, NB), 256>>>(x, p1w);
    {
        long total = (long)NB * CKD * (KA / 8);
        prep_a1_kernel<<<(int)((total + 255) / 256), 256>>>(x);
    }

    // GEMM-A: 14 x 2 x 32 = 896 CTAs ~ 3.03 waves
    gemm_a_kernel<<<dim3(CKD / 128, CC / 128, NB * NSPL), 256, SMEM_A>>>();

    t7_build_kernel<<<dim3(CC, NB), 256>>>();

    // GEMM-BC v2: 16 x 13 x 8 = 1664 CTAs, 2 N-tiles per CTA
    gemm_bc_kernel<<<dim3(CKD / 128 + CC / 128, 13, NB), 256, SMEM_BC>>>();

    combine_kernel<<<dim3((HWP + 255) / 256, CC, NB), 256>>>(out);
}